// round 1
// baseline (speedup 1.0000x reference)
#include <cuda_runtime.h>
#include <cstdint>

#define N_USERS    100000
#define N_ENTITIES 100000
#define N_NODES    200000
#define D          64
#define E_KG       1500000
#define E_PREF     1500000
#define NNZ        1000000

// ---------------- scratch (no allocation allowed) ----------------
__device__ float g_ent_cur [(size_t)N_ENTITIES * D];  // current entity embedding
__device__ float g_ent_acc [(size_t)N_ENTITIES * D];  // entity scatter accumulator
__device__ float g_node_cur[(size_t)N_NODES    * D];  // current node embedding
__device__ float g_node_acc[(size_t)N_NODES    * D];  // node scatter accumulator
__device__ float g_user_acc[(size_t)N_USERS    * D];  // interaction accumulator
__device__ float g_ent_inv [N_ENTITIES];              // 1 / max(deg, 1)
__device__ int   g_ent_cnt [N_ENTITIES];

// vector reduction (no return) — 1 instr covers 4 floats
__device__ __forceinline__ void red_add_v4(float* addr, float4 v) {
    asm volatile("red.global.add.v4.f32 [%0], {%1, %2, %3, %4};"
                 :: "l"(addr), "f"(v.x), "f"(v.y), "f"(v.z), "f"(v.w)
                 : "memory");
}

// ---------------- kernels ----------------

__global__ void count_kernel(const int* __restrict__ head, int E, int* __restrict__ cnt) {
    int i = blockIdx.x * blockDim.x + threadIdx.x;
    if (i < E) atomicAdd(&cnt[head[i]], 1);
}

__global__ void inv_kernel(const int* __restrict__ cnt, float* __restrict__ inv, int n) {
    int i = blockIdx.x * blockDim.x + threadIdx.x;
    if (i < n) inv[i] = 1.0f / fmaxf((float)cnt[i], 1.0f);
}

// KG scatter: ent_acc[head] += ent_cur[tail] * weight[type-1]
// 16 threads per edge, float4 per thread (256B row).
__global__ void scatter_kg(const int* __restrict__ tail, const int* __restrict__ head,
                           const int* __restrict__ etype, const float* __restrict__ weight) {
    long t = (long)blockIdx.x * blockDim.x + threadIdx.x;
    int e   = (int)(t >> 4);
    int sub = (int)(t & 15);
    if (e >= E_KG) return;
    int ta = tail[e];
    int he = head[e];
    int ty = etype[e] - 1;
    float4 x = *(const float4*)(g_ent_cur + (size_t)ta * D + sub * 4);
    float4 w = *(const float4*)(weight    + (size_t)ty * D + sub * 4);
    float4 p = make_float4(x.x * w.x, x.y * w.y, x.z * w.z, x.w * w.w);
    red_add_v4(g_ent_acc + (size_t)he * D + sub * 4, p);
}

// Preference scatter: node_acc[ehead] += all_embed[etail] * extra_weight[etype]
// all_embed = [node_cur[:N_USERS] ; ent_cur]
__global__ void scatter_pref(const int* __restrict__ tail, const int* __restrict__ head,
                             const int* __restrict__ etype, const float* __restrict__ eweight) {
    long t = (long)blockIdx.x * blockDim.x + threadIdx.x;
    int e   = (int)(t >> 4);
    int sub = (int)(t & 15);
    if (e >= E_PREF) return;
    int ta = tail[e];
    int he = head[e];
    int ty = etype[e];
    const float* src = (ta < N_USERS) ? (g_node_cur + (size_t)ta * D)
                                      : (g_ent_cur  + (size_t)(ta - N_USERS) * D);
    float4 x = *(const float4*)(src + sub * 4);
    float4 w = *(const float4*)(eweight + (size_t)ty * D + sub * 4);
    float4 p = make_float4(x.x * w.x, x.y * w.y, x.z * w.z, x.w * w.w);
    red_add_v4(g_node_acc + (size_t)he * D + sub * 4, p);
}

// Interaction: user_acc[row] += val * (ent_acc[col] * ent_inv[col])
// (ent_inv folds the scatter-mean divide; l2norm elsewhere is scale-invariant)
__global__ void scatter_interact(const int* __restrict__ rows, const int* __restrict__ cols,
                                 const float* __restrict__ vals) {
    long t = (long)blockIdx.x * blockDim.x + threadIdx.x;
    int e   = (int)(t >> 4);
    int sub = (int)(t & 15);
    if (e >= NNZ) return;
    int r = rows[e];
    int c = cols[e];
    float s = vals[e] * g_ent_inv[c];
    float4 x = *(const float4*)(g_ent_acc + (size_t)c * D + sub * 4);
    float4 p = make_float4(x.x * s, x.y * s, x.z * s, x.w * s);
    red_add_v4(g_user_acc + (size_t)r * D + sub * 4, p);
}

// Row-wise L2 normalize: one warp per row, float2 per lane.
// dst (optional): write normalized row. res (optional): res += normalized row.
__global__ void norm_rows(const float* __restrict__ src, float* __restrict__ dst,
                          float* __restrict__ res, int nrows) {
    int w    = (blockIdx.x * blockDim.x + threadIdx.x) >> 5;
    int lane = threadIdx.x & 31;
    if (w >= nrows) return;
    float2 v = ((const float2*)(src + (size_t)w * D))[lane];
    float ss = v.x * v.x + v.y * v.y;
    #pragma unroll
    for (int o = 16; o; o >>= 1) ss += __shfl_xor_sync(0xffffffffu, ss, o);
    float s = 1.0f / fmaxf(sqrtf(ss), 1e-12f);
    float2 r = make_float2(v.x * s, v.y * s);
    if (dst) ((float2*)(dst + (size_t)w * D))[lane] = r;
    if (res) {
        float2 a = ((float2*)(res + (size_t)w * D))[lane];
        ((float2*)(res + (size_t)w * D))[lane] = make_float2(a.x + r.x, a.y + r.y);
    }
}

// ---------------- launch ----------------

extern "C" void kernel_launch(void* const* d_in, const int* in_sizes, int n_in,
                              void* d_out, int out_size) {
    const float* user_emb        = (const float*)d_in[0];
    const float* entity_emb      = (const float*)d_in[1];
    const float* weight          = (const float*)d_in[2];
    const float* extra_weight    = (const float*)d_in[3];
    const float* interact_vals   = (const float*)d_in[4];
    const int*   edge_index      = (const int*)d_in[5];
    const int*   edge_type       = (const int*)d_in[6];
    const int*   extra_edge_index= (const int*)d_in[7];
    const int*   extra_edge_type = (const int*)d_in[8];
    const int*   interact_idx    = (const int*)d_in[9];
    float* out = (float*)d_out;

    const int* kg_head = edge_index;               // row 0
    const int* kg_tail = edge_index + E_KG;        // row 1
    const int* pf_head = extra_edge_index;
    const int* pf_tail = extra_edge_index + E_PREF;
    const int* it_rows = interact_idx;
    const int* it_cols = interact_idx + NNZ;

    float *ent_cur, *ent_acc, *node_cur, *node_acc, *user_acc, *ent_inv;
    int* ent_cnt;
    cudaGetSymbolAddress((void**)&ent_cur,  g_ent_cur);
    cudaGetSymbolAddress((void**)&ent_acc,  g_ent_acc);
    cudaGetSymbolAddress((void**)&node_cur, g_node_cur);
    cudaGetSymbolAddress((void**)&node_acc, g_node_acc);
    cudaGetSymbolAddress((void**)&user_acc, g_user_acc);
    cudaGetSymbolAddress((void**)&ent_inv,  g_ent_inv);
    cudaGetSymbolAddress((void**)&ent_cnt,  g_ent_cnt);

    const size_t ENT_BYTES  = (size_t)N_ENTITIES * D * sizeof(float);
    const size_t USER_BYTES = (size_t)N_USERS    * D * sizeof(float);
    const size_t NODE_BYTES = (size_t)N_NODES    * D * sizeof(float);

    // d_out layout: [user_res (100k x 64) | entity_final (100k x 64) | node_res (200k x 64)]
    float* out_user = out;                                    // user_res
    float* out_ent  = out + (size_t)N_USERS * D;              // final entity_emb
    float* out_node = out + (size_t)N_NODES * D;              // node_res

    // ---- init state ----
    cudaMemcpyAsync(ent_cur, entity_emb, ENT_BYTES, cudaMemcpyDeviceToDevice);
    cudaMemcpyAsync(node_cur, user_emb, USER_BYTES, cudaMemcpyDeviceToDevice);
    cudaMemcpyAsync(node_cur + (size_t)N_USERS * D, entity_emb, ENT_BYTES, cudaMemcpyDeviceToDevice);
    cudaMemcpyAsync(out_user, user_emb, USER_BYTES, cudaMemcpyDeviceToDevice);   // user_res = user_emb
    cudaMemcpyAsync(out_node, user_emb, USER_BYTES, cudaMemcpyDeviceToDevice);   // node_res = concat(...)
    cudaMemcpyAsync(out_node + (size_t)N_USERS * D, entity_emb, ENT_BYTES, cudaMemcpyDeviceToDevice);

    // entity degree (hop-invariant)
    cudaMemsetAsync(ent_cnt, 0, N_ENTITIES * sizeof(int));
    count_kernel<<<(E_KG + 255) / 256, 256>>>(kg_head, E_KG, ent_cnt);
    inv_kernel<<<(N_ENTITIES + 255) / 256, 256>>>(ent_cnt, ent_inv, N_ENTITIES);

    const int KG_BLOCKS   = (int)(((long)E_KG   * 16 + 255) / 256);
    const int PF_BLOCKS   = (int)(((long)E_PREF * 16 + 255) / 256);
    const int IT_BLOCKS   = (int)(((long)NNZ    * 16 + 255) / 256);
    const int NORM_ENT_B  = (N_ENTITIES * 32 + 255) / 256;
    const int NORM_NODE_B = (N_NODES    * 32 + 255) / 256;
    const int NORM_USER_B = (N_USERS    * 32 + 255) / 256;

    for (int hop = 0; hop < 2; hop++) {
        cudaMemsetAsync(ent_acc,  0, ENT_BYTES);
        cudaMemsetAsync(node_acc, 0, NODE_BYTES);
        cudaMemsetAsync(user_acc, 0, USER_BYTES);

        scatter_kg  <<<KG_BLOCKS, 256>>>(kg_tail, kg_head, edge_type, weight);
        scatter_pref<<<PF_BLOCKS, 256>>>(pf_tail, pf_head, extra_edge_type, extra_weight);
        scatter_interact<<<IT_BLOCKS, 256>>>(it_rows, it_cols, interact_vals);

        // entity_emb <- l2norm(entity_agg)  (scale-invariant: skip the /deg)
        norm_rows<<<NORM_ENT_B, 256>>>(ent_acc, ent_cur, nullptr, N_ENTITIES);
        // node_emb <- l2norm(node_agg); node_res += node_emb
        norm_rows<<<NORM_NODE_B, 256>>>(node_acc, node_cur, out_node, N_NODES);
        // user_res += l2norm(user_agg)
        norm_rows<<<NORM_USER_B, 256>>>(user_acc, nullptr, out_user, N_USERS);
    }

    // gcn_res second half = final entity_emb
    cudaMemcpyAsync(out_ent, ent_cur, ENT_BYTES, cudaMemcpyDeviceToDevice);
}

// round 2
// speedup vs baseline: 1.3631x; 1.3631x over previous
#include <cuda_runtime.h>
#include <cstdint>

#define N_USERS    100000
#define N_ENTITIES 100000
#define N_NODES    200000
#define D          64
#define E_KG       1500000
#define E_PREF     1500000
#define NNZ        1000000

// ---------------- scratch (no allocation allowed) ----------------
__device__ float g_ent_a   [(size_t)N_ENTITIES * D];   // entity embedding ping
__device__ float g_ent_b   [(size_t)N_ENTITIES * D];   // entity embedding pong
__device__ float g_ent_mean[(size_t)N_ENTITIES * D];   // scatter-mean entity (for interact)
__device__ float g_usr_a   [(size_t)N_USERS    * D];   // node_emb user-half ping
__device__ float g_usr_b   [(size_t)N_USERS    * D];   // node_emb user-half pong

__device__ int  g_cnt    [N_NODES];
__device__ int  g_bsums  [1024];
__device__ int  g_offs_kg[N_ENTITIES + 1];
__device__ int  g_offs_pf[N_NODES    + 1];
__device__ int  g_offs_it[N_USERS    + 1];
__device__ int  g_cursor [N_NODES];
__device__ int2 g_ekg[E_KG];    // (tail, type-1)
__device__ int2 g_epf[E_PREF];  // (tail, type)
__device__ int2 g_eit[NNZ];     // (col, float_bits(val))

// ---------------- CSR build ----------------

__global__ void count_k(const int* __restrict__ head, int E, int* __restrict__ cnt) {
    int i = blockIdx.x * blockDim.x + threadIdx.x;
    if (i < E) atomicAdd(&cnt[head[i]], 1);
}

// per-block exclusive scan (1024 elems/block); writes partial exclusive + block sum
__global__ void scan_block_k(const int* __restrict__ cnt, int n,
                             int* __restrict__ offs, int* __restrict__ bsums) {
    __shared__ int sh[1024];
    int idx = blockIdx.x * 1024 + threadIdx.x;
    int v = (idx < n) ? cnt[idx] : 0;
    sh[threadIdx.x] = v;
    __syncthreads();
    #pragma unroll
    for (int off = 1; off < 1024; off <<= 1) {
        int t = (threadIdx.x >= off) ? sh[threadIdx.x - off] : 0;
        __syncthreads();
        sh[threadIdx.x] += t;
        __syncthreads();
    }
    if (idx < n) offs[idx] = sh[threadIdx.x] - v;  // exclusive, block-local
    if (threadIdx.x == 1023) bsums[blockIdx.x] = sh[1023];
}

__global__ void scan_final_k(int* __restrict__ bsums, int nb, int* __restrict__ offs,
                             int n, int total) {
    if (threadIdx.x == 0 && blockIdx.x == 0) {
        int run = 0;
        for (int b = 0; b < nb; b++) { int t = bsums[b]; bsums[b] = run; run += t; }
        offs[n] = total;
    }
}

__global__ void add_offs_k(int* __restrict__ offs, const int* __restrict__ bsums, int n) {
    int idx = blockIdx.x * 1024 + threadIdx.x;
    if (idx < n) offs[idx] += bsums[blockIdx.x];
}

__global__ void fill_edges_k(const int* __restrict__ head, const int* __restrict__ tail,
                             const int* __restrict__ type, int E, int typeBias,
                             int* __restrict__ cursor, int2* __restrict__ out) {
    int e = blockIdx.x * blockDim.x + threadIdx.x;
    if (e >= E) return;
    int p = atomicAdd(&cursor[head[e]], 1);
    out[p] = make_int2(tail[e], type[e] - typeBias);
}

__global__ void fill_it_k(const int* __restrict__ rows, const int* __restrict__ cols,
                          const float* __restrict__ vals,
                          int* __restrict__ cursor, int2* __restrict__ out) {
    int e = blockIdx.x * blockDim.x + threadIdx.x;
    if (e >= NNZ) return;
    int p = atomicAdd(&cursor[rows[e]], 1);
    out[p] = make_int2(cols[e], __float_as_int(vals[e]));
}

// ---------------- fused gather kernels (1 warp / dst row, float2 / lane) ------

__device__ __forceinline__ float warp_sumsq(float2 a) {
    float ss = a.x * a.x + a.y * a.y;
    #pragma unroll
    for (int o = 16; o; o >>= 1) ss += __shfl_xor_sync(0xffffffffu, ss, o);
    return ss;
}

// entity_agg row = sum(ent_prev[tail]*weight[type]); write mean (for interact)
// and l2norm (next-hop entity_emb).
__global__ void gather_kg(const float* __restrict__ ent_prev,
                          const float* __restrict__ weight,
                          const int* __restrict__ offs, const int2* __restrict__ edges,
                          float* __restrict__ ent_mean, float* __restrict__ ent_next) {
    int w    = (blockIdx.x * blockDim.x + threadIdx.x) >> 5;
    int lane = threadIdx.x & 31;
    if (w >= N_ENTITIES) return;
    int s = __ldg(&offs[w]), e = __ldg(&offs[w + 1]);
    float2 acc = make_float2(0.f, 0.f);
    int i = s;
    for (; i + 1 < e; i += 2) {
        int2 e0 = __ldg(&edges[i]);
        int2 e1 = __ldg(&edges[i + 1]);
        float2 x0 = __ldg((const float2*)(ent_prev + (size_t)e0.x * D) + lane);
        float2 w0 = __ldg((const float2*)(weight   + (size_t)e0.y * D) + lane);
        float2 x1 = __ldg((const float2*)(ent_prev + (size_t)e1.x * D) + lane);
        float2 w1 = __ldg((const float2*)(weight   + (size_t)e1.y * D) + lane);
        acc.x += x0.x * w0.x + x1.x * w1.x;
        acc.y += x0.y * w0.y + x1.y * w1.y;
    }
    if (i < e) {
        int2 e0 = __ldg(&edges[i]);
        float2 x0 = __ldg((const float2*)(ent_prev + (size_t)e0.x * D) + lane);
        float2 w0 = __ldg((const float2*)(weight   + (size_t)e0.y * D) + lane);
        acc.x += x0.x * w0.x;
        acc.y += x0.y * w0.y;
    }
    float m = 1.0f / fmaxf((float)(e - s), 1.0f);
    ((float2*)(ent_mean + (size_t)w * D))[lane] = make_float2(acc.x * m, acc.y * m);
    float sc = 1.0f / fmaxf(sqrtf(warp_sumsq(acc)), 1e-12f);
    ((float2*)(ent_next + (size_t)w * D))[lane] = make_float2(acc.x * sc, acc.y * sc);
}

// node_agg row = sum(all_embed[tail]*extra_weight[type]); l2norm;
// store user-half for next hop; accumulate into out_node res.
__global__ void gather_pref(const float* __restrict__ usr_prev,
                            const float* __restrict__ ent_prev,
                            const float* __restrict__ eweight,
                            const int* __restrict__ offs, const int2* __restrict__ edges,
                            float* __restrict__ usr_next, float* __restrict__ out_node) {
    int w    = (blockIdx.x * blockDim.x + threadIdx.x) >> 5;
    int lane = threadIdx.x & 31;
    if (w >= N_NODES) return;
    int s = __ldg(&offs[w]), e = __ldg(&offs[w + 1]);
    float2 acc = make_float2(0.f, 0.f);
    int i = s;
    for (; i + 1 < e; i += 2) {
        int2 e0 = __ldg(&edges[i]);
        int2 e1 = __ldg(&edges[i + 1]);
        const float* s0 = (e0.x < N_USERS) ? (usr_prev + (size_t)e0.x * D)
                                           : (ent_prev + (size_t)(e0.x - N_USERS) * D);
        const float* s1 = (e1.x < N_USERS) ? (usr_prev + (size_t)e1.x * D)
                                           : (ent_prev + (size_t)(e1.x - N_USERS) * D);
        float2 x0 = __ldg((const float2*)s0 + lane);
        float2 w0 = __ldg((const float2*)(eweight + (size_t)e0.y * D) + lane);
        float2 x1 = __ldg((const float2*)s1 + lane);
        float2 w1 = __ldg((const float2*)(eweight + (size_t)e1.y * D) + lane);
        acc.x += x0.x * w0.x + x1.x * w1.x;
        acc.y += x0.y * w0.y + x1.y * w1.y;
    }
    if (i < e) {
        int2 e0 = __ldg(&edges[i]);
        const float* s0 = (e0.x < N_USERS) ? (usr_prev + (size_t)e0.x * D)
                                           : (ent_prev + (size_t)(e0.x - N_USERS) * D);
        float2 x0 = __ldg((const float2*)s0 + lane);
        float2 w0 = __ldg((const float2*)(eweight + (size_t)e0.y * D) + lane);
        acc.x += x0.x * w0.x;
        acc.y += x0.y * w0.y;
    }
    float sc = 1.0f / fmaxf(sqrtf(warp_sumsq(acc)), 1e-12f);
    float2 r = make_float2(acc.x * sc, acc.y * sc);
    if (w < N_USERS) ((float2*)(usr_next + (size_t)w * D))[lane] = r;
    float2* o = (float2*)(out_node + (size_t)w * D) + lane;
    float2 a = *o;
    *o = make_float2(a.x + r.x, a.y + r.y);
}

// user row = sum(val * ent_mean[col]); l2norm; accumulate into out_user res.
__global__ void gather_it(const float* __restrict__ ent_mean,
                          const int* __restrict__ offs, const int2* __restrict__ edges,
                          float* __restrict__ out_user) {
    int w    = (blockIdx.x * blockDim.x + threadIdx.x) >> 5;
    int lane = threadIdx.x & 31;
    if (w >= N_USERS) return;
    int s = __ldg(&offs[w]), e = __ldg(&offs[w + 1]);
    float2 acc = make_float2(0.f, 0.f);
    int i = s;
    for (; i + 1 < e; i += 2) {
        int2 e0 = __ldg(&edges[i]);
        int2 e1 = __ldg(&edges[i + 1]);
        float  v0 = __int_as_float(e0.y);
        float  v1 = __int_as_float(e1.y);
        float2 x0 = __ldg((const float2*)(ent_mean + (size_t)e0.x * D) + lane);
        float2 x1 = __ldg((const float2*)(ent_mean + (size_t)e1.x * D) + lane);
        acc.x += v0 * x0.x + v1 * x1.x;
        acc.y += v0 * x0.y + v1 * x1.y;
    }
    if (i < e) {
        int2 e0 = __ldg(&edges[i]);
        float  v0 = __int_as_float(e0.y);
        float2 x0 = __ldg((const float2*)(ent_mean + (size_t)e0.x * D) + lane);
        acc.x += v0 * x0.x;
        acc.y += v0 * x0.y;
    }
    float sc = 1.0f / fmaxf(sqrtf(warp_sumsq(acc)), 1e-12f);
    float2* o = (float2*)(out_user + (size_t)w * D) + lane;
    float2 a = *o;
    *o = make_float2(a.x + acc.x * sc, a.y + acc.y * sc);
}

// ---------------- launch ----------------

static void build_csr(const int* head, int E, int n, int* offs, int* cursor,
                      int* cnt, int* bsums) {
    cudaMemsetAsync(cnt, 0, n * sizeof(int));
    count_k<<<(E + 255) / 256, 256>>>(head, E, cnt);
    int nb = (n + 1023) / 1024;
    scan_block_k<<<nb, 1024>>>(cnt, n, offs, bsums);
    scan_final_k<<<1, 32>>>(bsums, nb, offs, n, E);
    add_offs_k<<<nb, 1024>>>(offs, bsums, n);
    cudaMemcpyAsync(cursor, offs, n * sizeof(int), cudaMemcpyDeviceToDevice);
}

extern "C" void kernel_launch(void* const* d_in, const int* in_sizes, int n_in,
                              void* d_out, int out_size) {
    const float* user_emb         = (const float*)d_in[0];
    const float* entity_emb       = (const float*)d_in[1];
    const float* weight           = (const float*)d_in[2];
    const float* extra_weight     = (const float*)d_in[3];
    const float* interact_vals    = (const float*)d_in[4];
    const int*   edge_index       = (const int*)d_in[5];
    const int*   edge_type        = (const int*)d_in[6];
    const int*   extra_edge_index = (const int*)d_in[7];
    const int*   extra_edge_type  = (const int*)d_in[8];
    const int*   interact_idx     = (const int*)d_in[9];
    float* out = (float*)d_out;

    const int* kg_head = edge_index;
    const int* kg_tail = edge_index + E_KG;
    const int* pf_head = extra_edge_index;
    const int* pf_tail = extra_edge_index + E_PREF;
    const int* it_rows = interact_idx;
    const int* it_cols = interact_idx + NNZ;

    float *ent_a, *ent_b, *ent_mean, *usr_a, *usr_b;
    int *cnt, *bsums, *offs_kg, *offs_pf, *offs_it, *cursor;
    int2 *ekg, *epf, *eit;
    cudaGetSymbolAddress((void**)&ent_a,    g_ent_a);
    cudaGetSymbolAddress((void**)&ent_b,    g_ent_b);
    cudaGetSymbolAddress((void**)&ent_mean, g_ent_mean);
    cudaGetSymbolAddress((void**)&usr_a,    g_usr_a);
    cudaGetSymbolAddress((void**)&usr_b,    g_usr_b);
    cudaGetSymbolAddress((void**)&cnt,      g_cnt);
    cudaGetSymbolAddress((void**)&bsums,    g_bsums);
    cudaGetSymbolAddress((void**)&offs_kg,  g_offs_kg);
    cudaGetSymbolAddress((void**)&offs_pf,  g_offs_pf);
    cudaGetSymbolAddress((void**)&offs_it,  g_offs_it);
    cudaGetSymbolAddress((void**)&cursor,   g_cursor);
    cudaGetSymbolAddress((void**)&ekg,      g_ekg);
    cudaGetSymbolAddress((void**)&epf,      g_epf);
    cudaGetSymbolAddress((void**)&eit,      g_eit);

    const size_t ENT_BYTES  = (size_t)N_ENTITIES * D * sizeof(float);
    const size_t USER_BYTES = (size_t)N_USERS    * D * sizeof(float);

    // d_out layout: [user_res | entity_final | node_res]
    float* out_user = out;
    float* out_ent  = out + (size_t)N_USERS * D;
    float* out_node = out + (size_t)N_NODES * D;

    // ---- init state + output residuals ----
    cudaMemcpyAsync(ent_a, entity_emb, ENT_BYTES, cudaMemcpyDeviceToDevice);
    cudaMemcpyAsync(usr_a, user_emb,   USER_BYTES, cudaMemcpyDeviceToDevice);
    cudaMemcpyAsync(out_user, user_emb, USER_BYTES, cudaMemcpyDeviceToDevice);
    cudaMemcpyAsync(out_node, user_emb, USER_BYTES, cudaMemcpyDeviceToDevice);
    cudaMemcpyAsync(out_node + (size_t)N_USERS * D, entity_emb, ENT_BYTES,
                    cudaMemcpyDeviceToDevice);

    // ---- CSR builds ----
    build_csr(kg_head, E_KG, N_ENTITIES, offs_kg, cursor, cnt, bsums);
    fill_edges_k<<<(E_KG + 255) / 256, 256>>>(kg_head, kg_tail, edge_type, E_KG, 1,
                                              cursor, ekg);
    build_csr(pf_head, E_PREF, N_NODES, offs_pf, cursor, cnt, bsums);
    fill_edges_k<<<(E_PREF + 255) / 256, 256>>>(pf_head, pf_tail, extra_edge_type, E_PREF, 0,
                                                cursor, epf);
    build_csr(it_rows, NNZ, N_USERS, offs_it, cursor, cnt, bsums);
    fill_it_k<<<(NNZ + 255) / 256, 256>>>(it_rows, it_cols, interact_vals, cursor, eit);

    const int GB_ENT  = (N_ENTITIES * 32 + 255) / 256;
    const int GB_NODE = (N_NODES    * 32 + 255) / 256;
    const int GB_USER = (N_USERS    * 32 + 255) / 256;

    // ---- hop 0 ----
    gather_kg  <<<GB_ENT,  256>>>(ent_a, weight, offs_kg, ekg, ent_mean, ent_b);
    gather_pref<<<GB_NODE, 256>>>(usr_a, ent_a, extra_weight, offs_pf, epf, usr_b, out_node);
    gather_it  <<<GB_USER, 256>>>(ent_mean, offs_it, eit, out_user);

    // ---- hop 1 (final entity l2norm written straight to d_out) ----
    gather_kg  <<<GB_ENT,  256>>>(ent_b, weight, offs_kg, ekg, ent_mean, out_ent);
    gather_pref<<<GB_NODE, 256>>>(usr_b, ent_b, extra_weight, offs_pf, epf, usr_a, out_node);
    gather_it  <<<GB_USER, 256>>>(ent_mean, offs_it, eit, out_user);
}

// round 3
// speedup vs baseline: 2.0324x; 1.4910x over previous
#include <cuda_runtime.h>
#include <cstdint>

#define N_USERS    100000
#define N_ENTITIES 100000
#define N_NODES    200000
#define D          64
#define E_KG       1500000
#define E_PREF     1500000
#define NNZ        1000000

// ---------------- scratch (no device allocation allowed) ----------------
__device__ float g_ent_a[(size_t)N_ENTITIES * D];
__device__ float g_ent_b[(size_t)N_ENTITIES * D];
__device__ float g_usr_a[(size_t)N_USERS * D];
__device__ float g_usr_b[(size_t)N_USERS * D];
__device__ float g_fent [N_ENTITIES];            // ||acc|| / deg  (mean reconstruct)

__device__ int  g_cnt_kg[N_ENTITIES];
__device__ int  g_cnt_pf[N_NODES];
__device__ int  g_cnt_it[N_USERS];
__device__ int  g_bs_kg[1024];
__device__ int  g_bs_pf[1024];
__device__ int  g_bs_it[1024];
__device__ int  g_offs_kg[N_ENTITIES + 1];
__device__ int  g_offs_pf[N_NODES + 1];
__device__ int  g_offs_it[N_USERS + 1];
__device__ int  g_cur_kg[N_ENTITIES];
__device__ int  g_cur_pf[N_NODES];
__device__ int  g_cur_it[N_USERS];
__device__ int2 g_ekg[E_KG];    // (tail, type-1)
__device__ int2 g_epf[E_PREF];  // (tail, type)
__device__ int2 g_eit[NNZ];     // (col, float_bits(val))

// ---------------- CSR build ----------------

__global__ void count_k(const int* __restrict__ head, int E, int* __restrict__ cnt) {
    int i = blockIdx.x * blockDim.x + threadIdx.x;
    if (i < E) atomicAdd(&cnt[head[i]], 1);
}

__global__ void scan_block_k(const int* __restrict__ cnt, int n,
                             int* __restrict__ offs, int* __restrict__ bsums) {
    __shared__ int sh[1024];
    int idx = blockIdx.x * 1024 + threadIdx.x;
    int v = (idx < n) ? cnt[idx] : 0;
    sh[threadIdx.x] = v;
    __syncthreads();
    #pragma unroll
    for (int off = 1; off < 1024; off <<= 1) {
        int t = (threadIdx.x >= off) ? sh[threadIdx.x - off] : 0;
        __syncthreads();
        sh[threadIdx.x] += t;
        __syncthreads();
    }
    if (idx < n) offs[idx] = sh[threadIdx.x] - v;  // exclusive, block-local
    if (threadIdx.x == 1023) bsums[blockIdx.x] = sh[1023];
}

__global__ void scan_final_k(int* __restrict__ bsums, int nb, int* __restrict__ offs,
                             int n, int total) {
    if (threadIdx.x == 0 && blockIdx.x == 0) {
        int run = 0;
        for (int b = 0; b < nb; b++) { int t = bsums[b]; bsums[b] = run; run += t; }
        offs[n] = total;
    }
}

// add block prefix; also write cursor copy
__global__ void add_offs_k(int* __restrict__ offs, int* __restrict__ cursor,
                           const int* __restrict__ bsums, int n) {
    int idx = blockIdx.x * 1024 + threadIdx.x;
    if (idx < n) {
        int v = offs[idx] + bsums[blockIdx.x];
        offs[idx] = v;
        cursor[idx] = v;
    }
}

__global__ void fill_edges_k(const int* __restrict__ head, const int* __restrict__ tail,
                             const int* __restrict__ type, int E, int typeBias,
                             int* __restrict__ cursor, int2* __restrict__ out) {
    int e = blockIdx.x * blockDim.x + threadIdx.x;
    if (e >= E) return;
    int p = atomicAdd(&cursor[head[e]], 1);
    out[p] = make_int2(tail[e], type[e] - typeBias);
}

__global__ void fill_it_k(const int* __restrict__ rows, const int* __restrict__ cols,
                          const float* __restrict__ vals,
                          int* __restrict__ cursor, int2* __restrict__ out) {
    int e = blockIdx.x * blockDim.x + threadIdx.x;
    if (e >= NNZ) return;
    int p = atomicAdd(&cursor[rows[e]], 1);
    out[p] = make_int2(cols[e], __float_as_int(vals[e]));
}

// ------------- fused gathers: 16 lanes / row, float4 / lane -------------

__device__ __forceinline__ float group_sumsq16(float4 a) {
    float ss = a.x * a.x + a.y * a.y + a.z * a.z + a.w * a.w;
    #pragma unroll
    for (int o = 8; o; o >>= 1) ss += __shfl_xor_sync(0xffffffffu, ss, o);
    return ss;
}

// entity: acc = sum(ent_prev[tail]*weight[type]); ent_next = l2norm(acc);
// f_out = max(||acc||,eps)/max(deg,1)  so that mean = ent_next * f_out.
__global__ void __launch_bounds__(256)
gather_kg(const float* __restrict__ ent_prev, const float* __restrict__ weight,
          const int* __restrict__ offs, const int2* __restrict__ edges,
          float* __restrict__ ent_next, float* __restrict__ f_out) {
    int t  = blockIdx.x * blockDim.x + threadIdx.x;
    int w  = t >> 4, ln = t & 15;
    if (w >= N_ENTITIES) return;
    int s = __ldg(&offs[w]), e = __ldg(&offs[w + 1]);
    float4 acc = make_float4(0.f, 0.f, 0.f, 0.f);
    int i = s;
    for (; i + 1 < e; i += 2) {
        int2 e0 = __ldg(&edges[i]);
        int2 e1 = __ldg(&edges[i + 1]);
        float4 x0 = __ldg((const float4*)(ent_prev + (size_t)e0.x * D) + ln);
        float4 w0 = __ldg((const float4*)(weight   + (size_t)e0.y * D) + ln);
        float4 x1 = __ldg((const float4*)(ent_prev + (size_t)e1.x * D) + ln);
        float4 w1 = __ldg((const float4*)(weight   + (size_t)e1.y * D) + ln);
        acc.x += x0.x * w0.x + x1.x * w1.x;
        acc.y += x0.y * w0.y + x1.y * w1.y;
        acc.z += x0.z * w0.z + x1.z * w1.z;
        acc.w += x0.w * w0.w + x1.w * w1.w;
    }
    if (i < e) {
        int2 e0 = __ldg(&edges[i]);
        float4 x0 = __ldg((const float4*)(ent_prev + (size_t)e0.x * D) + ln);
        float4 w0 = __ldg((const float4*)(weight   + (size_t)e0.y * D) + ln);
        acc.x += x0.x * w0.x; acc.y += x0.y * w0.y;
        acc.z += x0.z * w0.z; acc.w += x0.w * w0.w;
    }
    float nrm = fmaxf(sqrtf(group_sumsq16(acc)), 1e-12f);
    float sc = 1.0f / nrm;
    ((float4*)(ent_next + (size_t)w * D))[ln] =
        make_float4(acc.x * sc, acc.y * sc, acc.z * sc, acc.w * sc);
    if (ln == 0) f_out[w] = nrm / fmaxf((float)(e - s), 1.0f);
}

// node: r = l2norm(sum(all_embed[tail]*eweight[type]))
// mode 0: out_node = r; usr_next = r (for w < N_USERS)
// mode 1: out_node = out_node + init + r   (init = concat(user_emb0, entity_emb0))
__global__ void __launch_bounds__(256)
gather_pref(const float* __restrict__ usr_prev, const float* __restrict__ ent_prev,
            const float* __restrict__ eweight,
            const int* __restrict__ offs, const int2* __restrict__ edges,
            float* __restrict__ usr_next, float* __restrict__ out_node,
            const float* __restrict__ user0, const float* __restrict__ ent0, int mode) {
    int t  = blockIdx.x * blockDim.x + threadIdx.x;
    int w  = t >> 4, ln = t & 15;
    if (w >= N_NODES) return;
    int s = __ldg(&offs[w]), e = __ldg(&offs[w + 1]);
    float4 acc = make_float4(0.f, 0.f, 0.f, 0.f);
    int i = s;
    for (; i + 1 < e; i += 2) {
        int2 e0 = __ldg(&edges[i]);
        int2 e1 = __ldg(&edges[i + 1]);
        const float* s0 = (e0.x < N_USERS) ? (usr_prev + (size_t)e0.x * D)
                                           : (ent_prev + (size_t)(e0.x - N_USERS) * D);
        const float* s1 = (e1.x < N_USERS) ? (usr_prev + (size_t)e1.x * D)
                                           : (ent_prev + (size_t)(e1.x - N_USERS) * D);
        float4 x0 = __ldg((const float4*)s0 + ln);
        float4 w0 = __ldg((const float4*)(eweight + (size_t)e0.y * D) + ln);
        float4 x1 = __ldg((const float4*)s1 + ln);
        float4 w1 = __ldg((const float4*)(eweight + (size_t)e1.y * D) + ln);
        acc.x += x0.x * w0.x + x1.x * w1.x;
        acc.y += x0.y * w0.y + x1.y * w1.y;
        acc.z += x0.z * w0.z + x1.z * w1.z;
        acc.w += x0.w * w0.w + x1.w * w1.w;
    }
    if (i < e) {
        int2 e0 = __ldg(&edges[i]);
        const float* s0 = (e0.x < N_USERS) ? (usr_prev + (size_t)e0.x * D)
                                           : (ent_prev + (size_t)(e0.x - N_USERS) * D);
        float4 x0 = __ldg((const float4*)s0 + ln);
        float4 w0 = __ldg((const float4*)(eweight + (size_t)e0.y * D) + ln);
        acc.x += x0.x * w0.x; acc.y += x0.y * w0.y;
        acc.z += x0.z * w0.z; acc.w += x0.w * w0.w;
    }
    float sc = 1.0f / fmaxf(sqrtf(group_sumsq16(acc)), 1e-12f);
    float4 r = make_float4(acc.x * sc, acc.y * sc, acc.z * sc, acc.w * sc);
    float4* o = (float4*)(out_node + (size_t)w * D) + ln;
    if (mode == 0) {
        if (w < N_USERS) ((float4*)(usr_next + (size_t)w * D))[ln] = r;
        *o = r;
    } else {
        const float* ip = (w < N_USERS) ? (user0 + (size_t)w * D)
                                        : (ent0 + (size_t)(w - N_USERS) * D);
        float4 iv = __ldg((const float4*)ip + ln);
        float4 a = *o;
        *o = make_float4(a.x + iv.x + r.x, a.y + iv.y + r.y,
                         a.z + iv.z + r.z, a.w + iv.w + r.w);
    }
}

// user: r = l2norm(sum(val * f[col] * ent_norm[col]))
// mode 0: out_user = user_emb0 + r ;  mode 1: out_user += r
__global__ void __launch_bounds__(256)
gather_it(const float* __restrict__ ent_norm, const float* __restrict__ f,
          const int* __restrict__ offs, const int2* __restrict__ edges,
          float* __restrict__ out_user, const float* __restrict__ user0, int mode) {
    int t  = blockIdx.x * blockDim.x + threadIdx.x;
    int w  = t >> 4, ln = t & 15;
    if (w >= N_USERS) return;
    int s = __ldg(&offs[w]), e = __ldg(&offs[w + 1]);
    float4 acc = make_float4(0.f, 0.f, 0.f, 0.f);
    int i = s;
    for (; i + 1 < e; i += 2) {
        int2 e0 = __ldg(&edges[i]);
        int2 e1 = __ldg(&edges[i + 1]);
        float v0 = __int_as_float(e0.y) * __ldg(&f[e0.x]);
        float v1 = __int_as_float(e1.y) * __ldg(&f[e1.x]);
        float4 x0 = __ldg((const float4*)(ent_norm + (size_t)e0.x * D) + ln);
        float4 x1 = __ldg((const float4*)(ent_norm + (size_t)e1.x * D) + ln);
        acc.x += v0 * x0.x + v1 * x1.x;
        acc.y += v0 * x0.y + v1 * x1.y;
        acc.z += v0 * x0.z + v1 * x1.z;
        acc.w += v0 * x0.w + v1 * x1.w;
    }
    if (i < e) {
        int2 e0 = __ldg(&edges[i]);
        float v0 = __int_as_float(e0.y) * __ldg(&f[e0.x]);
        float4 x0 = __ldg((const float4*)(ent_norm + (size_t)e0.x * D) + ln);
        acc.x += v0 * x0.x; acc.y += v0 * x0.y;
        acc.z += v0 * x0.z; acc.w += v0 * x0.w;
    }
    float sc = 1.0f / fmaxf(sqrtf(group_sumsq16(acc)), 1e-12f);
    float4* o = (float4*)(out_user + (size_t)w * D) + ln;
    if (mode == 0) {
        float4 u = __ldg((const float4*)(user0 + (size_t)w * D) + ln);
        *o = make_float4(u.x + acc.x * sc, u.y + acc.y * sc,
                         u.z + acc.z * sc, u.w + acc.w * sc);
    } else {
        float4 a = *o;
        *o = make_float4(a.x + acc.x * sc, a.y + acc.y * sc,
                         a.z + acc.z * sc, a.w + acc.w * sc);
    }
}

// ---------------- launch ----------------

static void build_csr(cudaStream_t st, const int* head, int E, int n,
                      int* offs, int* cursor, int* cnt, int* bsums) {
    cudaMemsetAsync(cnt, 0, n * sizeof(int), st);
    count_k<<<(E + 255) / 256, 256, 0, st>>>(head, E, cnt);
    int nb = (n + 1023) / 1024;
    scan_block_k<<<nb, 1024, 0, st>>>(cnt, n, offs, bsums);
    scan_final_k<<<1, 32, 0, st>>>(bsums, nb, offs, n, E);
    add_offs_k<<<nb, 1024, 0, st>>>(offs, cursor, bsums, n);
}

extern "C" void kernel_launch(void* const* d_in, const int* in_sizes, int n_in,
                              void* d_out, int out_size) {
    const float* user_emb         = (const float*)d_in[0];
    const float* entity_emb       = (const float*)d_in[1];
    const float* weight           = (const float*)d_in[2];
    const float* extra_weight     = (const float*)d_in[3];
    const float* interact_vals    = (const float*)d_in[4];
    const int*   edge_index       = (const int*)d_in[5];
    const int*   edge_type        = (const int*)d_in[6];
    const int*   extra_edge_index = (const int*)d_in[7];
    const int*   extra_edge_type  = (const int*)d_in[8];
    const int*   interact_idx     = (const int*)d_in[9];
    float* out = (float*)d_out;

    const int* kg_head = edge_index;
    const int* kg_tail = edge_index + E_KG;
    const int* pf_head = extra_edge_index;
    const int* pf_tail = extra_edge_index + E_PREF;
    const int* it_rows = interact_idx;
    const int* it_cols = interact_idx + NNZ;

    // one-time stream/event setup (first call is the uncaptured correctness run)
    static cudaStream_t sA = nullptr, sB = nullptr;
    static cudaEvent_t evFork, evEnt, evKG0, evIT, evPref;
    if (!sA) {
        cudaStreamCreateWithFlags(&sA, cudaStreamNonBlocking);
        cudaStreamCreateWithFlags(&sB, cudaStreamNonBlocking);
        cudaEventCreateWithFlags(&evFork, cudaEventDisableTiming);
        cudaEventCreateWithFlags(&evEnt,  cudaEventDisableTiming);
        cudaEventCreateWithFlags(&evKG0,  cudaEventDisableTiming);
        cudaEventCreateWithFlags(&evIT,   cudaEventDisableTiming);
        cudaEventCreateWithFlags(&evPref, cudaEventDisableTiming);
    }

    float *ent_a, *ent_b, *usr_a, *usr_b, *fent;
    int *cnt_kg, *cnt_pf, *cnt_it, *bs_kg, *bs_pf, *bs_it;
    int *offs_kg, *offs_pf, *offs_it, *cur_kg, *cur_pf, *cur_it;
    int2 *ekg, *epf, *eit;
    cudaGetSymbolAddress((void**)&ent_a,   g_ent_a);
    cudaGetSymbolAddress((void**)&ent_b,   g_ent_b);
    cudaGetSymbolAddress((void**)&usr_a,   g_usr_a);
    cudaGetSymbolAddress((void**)&usr_b,   g_usr_b);
    cudaGetSymbolAddress((void**)&fent,    g_fent);
    cudaGetSymbolAddress((void**)&cnt_kg,  g_cnt_kg);
    cudaGetSymbolAddress((void**)&cnt_pf,  g_cnt_pf);
    cudaGetSymbolAddress((void**)&cnt_it,  g_cnt_it);
    cudaGetSymbolAddress((void**)&bs_kg,   g_bs_kg);
    cudaGetSymbolAddress((void**)&bs_pf,   g_bs_pf);
    cudaGetSymbolAddress((void**)&bs_it,   g_bs_it);
    cudaGetSymbolAddress((void**)&offs_kg, g_offs_kg);
    cudaGetSymbolAddress((void**)&offs_pf, g_offs_pf);
    cudaGetSymbolAddress((void**)&offs_it, g_offs_it);
    cudaGetSymbolAddress((void**)&cur_kg,  g_cur_kg);
    cudaGetSymbolAddress((void**)&cur_pf,  g_cur_pf);
    cudaGetSymbolAddress((void**)&cur_it,  g_cur_it);
    cudaGetSymbolAddress((void**)&ekg,     g_ekg);
    cudaGetSymbolAddress((void**)&epf,     g_epf);
    cudaGetSymbolAddress((void**)&eit,     g_eit);

    const size_t ENT_BYTES  = (size_t)N_ENTITIES * D * sizeof(float);
    const size_t USER_BYTES = (size_t)N_USERS    * D * sizeof(float);

    float* out_user = out;                        // user_res
    float* out_ent  = out + (size_t)N_USERS * D;  // final normalized entity_emb
    float* out_node = out + (size_t)N_NODES * D;  // node_res

    const int GB_ENT  = (N_ENTITIES * 16 + 255) / 256;
    const int GB_NODE = (N_NODES    * 16 + 255) / 256;
    const int GB_USER = (N_USERS    * 16 + 255) / 256;

    // ---- fork ----
    cudaEventRecord(evFork, 0);
    cudaStreamWaitEvent(sA, evFork, 0);
    cudaStreamWaitEvent(sB, evFork, 0);

    // ---- stream B: interact CSR ----
    build_csr(sB, it_rows, NNZ, N_USERS, offs_it, cur_it, cnt_it, bs_it);
    fill_it_k<<<(NNZ + 255) / 256, 256, 0, sB>>>(it_rows, it_cols, interact_vals,
                                                 cur_it, eit);
    cudaEventRecord(evIT, sB);

    // ---- stream A: pref chain ----
    cudaMemcpyAsync(usr_a, user_emb, USER_BYTES, cudaMemcpyDeviceToDevice, sA);
    build_csr(sA, pf_head, E_PREF, N_NODES, offs_pf, cur_pf, cnt_pf, bs_pf);
    fill_edges_k<<<(E_PREF + 255) / 256, 256, 0, sA>>>(pf_head, pf_tail, extra_edge_type,
                                                       E_PREF, 0, cur_pf, epf);

    // ---- main: kg chain ----
    cudaMemcpyAsync(ent_a, entity_emb, ENT_BYTES, cudaMemcpyDeviceToDevice, 0);
    cudaEventRecord(evEnt, 0);
    build_csr(0, kg_head, E_KG, N_ENTITIES, offs_kg, cur_kg, cnt_kg, bs_kg);
    fill_edges_k<<<(E_KG + 255) / 256, 256, 0, 0>>>(kg_head, kg_tail, edge_type,
                                                    E_KG, 1, cur_kg, ekg);

    // hop 0 (main): entity agg
    gather_kg<<<GB_ENT, 256, 0, 0>>>(ent_a, weight, offs_kg, ekg, ent_b, fent);
    cudaEventRecord(evKG0, 0);

    // hop 0 (A): pref agg — needs ent_a copy
    cudaStreamWaitEvent(sA, evEnt, 0);
    gather_pref<<<GB_NODE, 256, 0, sA>>>(usr_a, ent_a, extra_weight, offs_pf, epf,
                                         usr_b, out_node, user_emb, entity_emb, 0);

    // hop 0 (main): interact — needs CSR_it + ent_b/fent
    cudaStreamWaitEvent(0, evIT, 0);
    gather_it<<<GB_USER, 256, 0, 0>>>(ent_b, fent, offs_it, eit, out_user, user_emb, 0);

    // hop 1 (main): entity agg → out_ent
    gather_kg<<<GB_ENT, 256, 0, 0>>>(ent_b, weight, offs_kg, ekg, out_ent, fent);
    gather_it<<<GB_USER, 256, 0, 0>>>(out_ent, fent, offs_it, eit, out_user, user_emb, 1);

    // hop 1 (A): pref agg — needs ent_b
    cudaStreamWaitEvent(sA, evKG0, 0);
    gather_pref<<<GB_NODE, 256, 0, sA>>>(usr_b, ent_b, extra_weight, offs_pf, epf,
                                         usr_a, out_node, user_emb, entity_emb, 1);
    cudaEventRecord(evPref, sA);

    // ---- join ----
    cudaStreamWaitEvent(0, evPref, 0);
}

// round 4
// speedup vs baseline: 2.1760x; 1.0707x over previous
#include <cuda_runtime.h>
#include <cstdint>

#define N_USERS    100000
#define N_ENTITIES 100000
#define N_NODES    200000
#define D          64
#define E_KG       1500000
#define E_PREF     1500000
#define NNZ        1000000

// ---------------- scratch (no device allocation allowed) ----------------
__device__ float g_ent_b [(size_t)N_ENTITIES * D];   // hop-0 normalized entity
__device__ float g_usr_b [(size_t)N_USERS * D];      // hop-0 node user-half
__device__ float g_usr_x [(size_t)N_USERS * D];      // dummy (never read)
__device__ float g_fent_a[N_ENTITIES];               // ||acc||/deg hop 0
__device__ float g_fent_b[N_ENTITIES];               // ||acc||/deg hop 1

__device__ int  g_cnt_kg[N_ENTITIES];
__device__ int  g_cnt_pf[N_NODES];
__device__ int  g_cnt_it[N_USERS];
__device__ int  g_bs_kg[1024];
__device__ int  g_bs_pf[1024];
__device__ int  g_bs_it[1024];
__device__ int  g_offs_kg[N_ENTITIES + 1];
__device__ int  g_offs_pf[N_NODES + 1];
__device__ int  g_offs_it[N_USERS + 1];
__device__ int  g_cur_kg[N_ENTITIES];
__device__ int  g_cur_pf[N_NODES];
__device__ int  g_cur_it[N_USERS];
__device__ int2 g_ekg[E_KG];    // (tail, type-1)
__device__ int2 g_epf[E_PREF];  // (tail, type)
__device__ int2 g_eit[NNZ];     // (col, float_bits(val))

// ---------------- CSR build ----------------

__global__ void count_k(const int* __restrict__ head, int E, int* __restrict__ cnt) {
    int i = blockIdx.x * blockDim.x + threadIdx.x;
    if (i < E) atomicAdd(&cnt[head[i]], 1);
}

__global__ void scan_block_k(const int* __restrict__ cnt, int n,
                             int* __restrict__ offs, int* __restrict__ bsums) {
    __shared__ int sh[1024];
    int idx = blockIdx.x * 1024 + threadIdx.x;
    int v = (idx < n) ? cnt[idx] : 0;
    sh[threadIdx.x] = v;
    __syncthreads();
    #pragma unroll
    for (int off = 1; off < 1024; off <<= 1) {
        int t = (threadIdx.x >= off) ? sh[threadIdx.x - off] : 0;
        __syncthreads();
        sh[threadIdx.x] += t;
        __syncthreads();
    }
    if (idx < n) offs[idx] = sh[threadIdx.x] - v;
    if (threadIdx.x == 1023) bsums[blockIdx.x] = sh[1023];
}

__global__ void scan_final_k(int* __restrict__ bsums, int nb, int* __restrict__ offs,
                             int n, int total) {
    if (threadIdx.x == 0 && blockIdx.x == 0) {
        int run = 0;
        for (int b = 0; b < nb; b++) { int t = bsums[b]; bsums[b] = run; run += t; }
        offs[n] = total;
    }
}

__global__ void add_offs_k(int* __restrict__ offs, int* __restrict__ cursor,
                           const int* __restrict__ bsums, int n) {
    int idx = blockIdx.x * 1024 + threadIdx.x;
    if (idx < n) {
        int v = offs[idx] + bsums[blockIdx.x];
        offs[idx] = v;
        cursor[idx] = v;
    }
}

__global__ void fill_edges_k(const int* __restrict__ head, const int* __restrict__ tail,
                             const int* __restrict__ type, int E, int typeBias,
                             int* __restrict__ cursor, int2* __restrict__ out) {
    int e = blockIdx.x * blockDim.x + threadIdx.x;
    if (e >= E) return;
    int p = atomicAdd(&cursor[head[e]], 1);
    out[p] = make_int2(tail[e], type[e] - typeBias);
}

__global__ void fill_it_k(const int* __restrict__ rows, const int* __restrict__ cols,
                          const float* __restrict__ vals,
                          int* __restrict__ cursor, int2* __restrict__ out) {
    int e = blockIdx.x * blockDim.x + threadIdx.x;
    if (e >= NNZ) return;
    int p = atomicAdd(&cursor[rows[e]], 1);
    out[p] = make_int2(cols[e], __float_as_int(vals[e]));
}

// ------------- fused gathers: 16 lanes / row, float4 / lane -------------

__device__ __forceinline__ float group_sumsq16(float4 a) {
    float ss = a.x * a.x + a.y * a.y + a.z * a.z + a.w * a.w;
    #pragma unroll
    for (int o = 8; o; o >>= 1) ss += __shfl_xor_sync(0xffffffffu, ss, o);
    return ss;
}

__device__ __forceinline__ void fma4(float4& acc, float4 x, float4 w) {
    acc.x += x.x * w.x; acc.y += x.y * w.y;
    acc.z += x.z * w.z; acc.w += x.w * w.w;
}

// entity: acc = sum(ent_prev[tail]*weight[type]); ent_next = l2norm(acc);
// f_out = max(||acc||,eps)/max(deg,1)   (mean = ent_next * f_out)
__global__ void __launch_bounds__(256)
gather_kg(const float* __restrict__ ent_prev, const float* __restrict__ weight,
          const int* __restrict__ offs, const int2* __restrict__ edges,
          float* __restrict__ ent_next, float* __restrict__ f_out) {
    int t  = blockIdx.x * blockDim.x + threadIdx.x;
    int w  = t >> 4, ln = t & 15;
    if (w >= N_ENTITIES) return;
    int s = __ldg(&offs[w]), e = __ldg(&offs[w + 1]);
    float4 acc = make_float4(0.f, 0.f, 0.f, 0.f);
    int i = s;
    for (; i + 3 < e; i += 4) {
        int2 e0 = __ldg(&edges[i]);
        int2 e1 = __ldg(&edges[i + 1]);
        int2 e2 = __ldg(&edges[i + 2]);
        int2 e3 = __ldg(&edges[i + 3]);
        float4 x0 = __ldg((const float4*)(ent_prev + (size_t)e0.x * D) + ln);
        float4 x1 = __ldg((const float4*)(ent_prev + (size_t)e1.x * D) + ln);
        float4 x2 = __ldg((const float4*)(ent_prev + (size_t)e2.x * D) + ln);
        float4 x3 = __ldg((const float4*)(ent_prev + (size_t)e3.x * D) + ln);
        float4 w0 = __ldg((const float4*)(weight + (size_t)e0.y * D) + ln);
        float4 w1 = __ldg((const float4*)(weight + (size_t)e1.y * D) + ln);
        float4 w2 = __ldg((const float4*)(weight + (size_t)e2.y * D) + ln);
        float4 w3 = __ldg((const float4*)(weight + (size_t)e3.y * D) + ln);
        fma4(acc, x0, w0); fma4(acc, x1, w1);
        fma4(acc, x2, w2); fma4(acc, x3, w3);
    }
    for (; i < e; i++) {
        int2 e0 = __ldg(&edges[i]);
        float4 x0 = __ldg((const float4*)(ent_prev + (size_t)e0.x * D) + ln);
        float4 w0 = __ldg((const float4*)(weight + (size_t)e0.y * D) + ln);
        fma4(acc, x0, w0);
    }
    float nrm = fmaxf(sqrtf(group_sumsq16(acc)), 1e-12f);
    float sc = 1.0f / nrm;
    ((float4*)(ent_next + (size_t)w * D))[ln] =
        make_float4(acc.x * sc, acc.y * sc, acc.z * sc, acc.w * sc);
    if (ln == 0) f_out[w] = nrm / fmaxf((float)(e - s), 1.0f);
}

// node: r = l2norm(sum(all_embed[tail]*eweight[type]))
// mode 0: out_node = r; usr_next = r (w < N_USERS)
// mode 1: out_node += init + r   (init = concat(user0, ent0))
__global__ void __launch_bounds__(256)
gather_pref(const float* __restrict__ usr_prev, const float* __restrict__ ent_prev,
            const float* __restrict__ eweight,
            const int* __restrict__ offs, const int2* __restrict__ edges,
            float* __restrict__ usr_next, float* __restrict__ out_node,
            const float* __restrict__ user0, const float* __restrict__ ent0, int mode) {
    int t  = blockIdx.x * blockDim.x + threadIdx.x;
    int w  = t >> 4, ln = t & 15;
    if (w >= N_NODES) return;
    int s = __ldg(&offs[w]), e = __ldg(&offs[w + 1]);
    float4 acc = make_float4(0.f, 0.f, 0.f, 0.f);
    int i = s;
    for (; i + 3 < e; i += 4) {
        int2 e0 = __ldg(&edges[i]);
        int2 e1 = __ldg(&edges[i + 1]);
        int2 e2 = __ldg(&edges[i + 2]);
        int2 e3 = __ldg(&edges[i + 3]);
        const float* s0 = (e0.x < N_USERS) ? (usr_prev + (size_t)e0.x * D)
                                           : (ent_prev + (size_t)(e0.x - N_USERS) * D);
        const float* s1 = (e1.x < N_USERS) ? (usr_prev + (size_t)e1.x * D)
                                           : (ent_prev + (size_t)(e1.x - N_USERS) * D);
        const float* s2 = (e2.x < N_USERS) ? (usr_prev + (size_t)e2.x * D)
                                           : (ent_prev + (size_t)(e2.x - N_USERS) * D);
        const float* s3 = (e3.x < N_USERS) ? (usr_prev + (size_t)e3.x * D)
                                           : (ent_prev + (size_t)(e3.x - N_USERS) * D);
        float4 x0 = __ldg((const float4*)s0 + ln);
        float4 x1 = __ldg((const float4*)s1 + ln);
        float4 x2 = __ldg((const float4*)s2 + ln);
        float4 x3 = __ldg((const float4*)s3 + ln);
        float4 w0 = __ldg((const float4*)(eweight + (size_t)e0.y * D) + ln);
        float4 w1 = __ldg((const float4*)(eweight + (size_t)e1.y * D) + ln);
        float4 w2 = __ldg((const float4*)(eweight + (size_t)e2.y * D) + ln);
        float4 w3 = __ldg((const float4*)(eweight + (size_t)e3.y * D) + ln);
        fma4(acc, x0, w0); fma4(acc, x1, w1);
        fma4(acc, x2, w2); fma4(acc, x3, w3);
    }
    for (; i < e; i++) {
        int2 e0 = __ldg(&edges[i]);
        const float* s0 = (e0.x < N_USERS) ? (usr_prev + (size_t)e0.x * D)
                                           : (ent_prev + (size_t)(e0.x - N_USERS) * D);
        float4 x0 = __ldg((const float4*)s0 + ln);
        float4 w0 = __ldg((const float4*)(eweight + (size_t)e0.y * D) + ln);
        fma4(acc, x0, w0);
    }
    float sc = 1.0f / fmaxf(sqrtf(group_sumsq16(acc)), 1e-12f);
    float4 r = make_float4(acc.x * sc, acc.y * sc, acc.z * sc, acc.w * sc);
    float4* o = (float4*)(out_node + (size_t)w * D) + ln;
    if (mode == 0) {
        if (w < N_USERS) ((float4*)(usr_next + (size_t)w * D))[ln] = r;
        *o = r;
    } else {
        const float* ip = (w < N_USERS) ? (user0 + (size_t)w * D)
                                        : (ent0 + (size_t)(w - N_USERS) * D);
        float4 iv = __ldg((const float4*)ip + ln);
        float4 a = *o;
        *o = make_float4(a.x + iv.x + r.x, a.y + iv.y + r.y,
                         a.z + iv.z + r.z, a.w + iv.w + r.w);
    }
}

// user: r = l2norm(sum(val * f[col] * ent_norm[col]))
// mode 0: out_user = user0 + r ; mode 1: out_user += r
__global__ void __launch_bounds__(256)
gather_it(const float* __restrict__ ent_norm, const float* __restrict__ f,
          const int* __restrict__ offs, const int2* __restrict__ edges,
          float* __restrict__ out_user, const float* __restrict__ user0, int mode) {
    int t  = blockIdx.x * blockDim.x + threadIdx.x;
    int w  = t >> 4, ln = t & 15;
    if (w >= N_USERS) return;
    int s = __ldg(&offs[w]), e = __ldg(&offs[w + 1]);
    float4 acc = make_float4(0.f, 0.f, 0.f, 0.f);
    int i = s;
    for (; i + 3 < e; i += 4) {
        int2 e0 = __ldg(&edges[i]);
        int2 e1 = __ldg(&edges[i + 1]);
        int2 e2 = __ldg(&edges[i + 2]);
        int2 e3 = __ldg(&edges[i + 3]);
        float v0 = __int_as_float(e0.y) * __ldg(&f[e0.x]);
        float v1 = __int_as_float(e1.y) * __ldg(&f[e1.x]);
        float v2 = __int_as_float(e2.y) * __ldg(&f[e2.x]);
        float v3 = __int_as_float(e3.y) * __ldg(&f[e3.x]);
        float4 x0 = __ldg((const float4*)(ent_norm + (size_t)e0.x * D) + ln);
        float4 x1 = __ldg((const float4*)(ent_norm + (size_t)e1.x * D) + ln);
        float4 x2 = __ldg((const float4*)(ent_norm + (size_t)e2.x * D) + ln);
        float4 x3 = __ldg((const float4*)(ent_norm + (size_t)e3.x * D) + ln);
        acc.x += v0 * x0.x + v1 * x1.x + v2 * x2.x + v3 * x3.x;
        acc.y += v0 * x0.y + v1 * x1.y + v2 * x2.y + v3 * x3.y;
        acc.z += v0 * x0.z + v1 * x1.z + v2 * x2.z + v3 * x3.z;
        acc.w += v0 * x0.w + v1 * x1.w + v2 * x2.w + v3 * x3.w;
    }
    for (; i < e; i++) {
        int2 e0 = __ldg(&edges[i]);
        float v0 = __int_as_float(e0.y) * __ldg(&f[e0.x]);
        float4 x0 = __ldg((const float4*)(ent_norm + (size_t)e0.x * D) + ln);
        acc.x += v0 * x0.x; acc.y += v0 * x0.y;
        acc.z += v0 * x0.z; acc.w += v0 * x0.w;
    }
    float sc = 1.0f / fmaxf(sqrtf(group_sumsq16(acc)), 1e-12f);
    float4* o = (float4*)(out_user + (size_t)w * D) + ln;
    if (mode == 0) {
        float4 u = __ldg((const float4*)(user0 + (size_t)w * D) + ln);
        *o = make_float4(u.x + acc.x * sc, u.y + acc.y * sc,
                         u.z + acc.z * sc, u.w + acc.w * sc);
    } else {
        float4 a = *o;
        *o = make_float4(a.x + acc.x * sc, a.y + acc.y * sc,
                         a.z + acc.z * sc, a.w + acc.w * sc);
    }
}

// ---------------- launch ----------------

static void build_csr(cudaStream_t st, const int* head, int E, int n,
                      int* offs, int* cursor, int* cnt, int* bsums) {
    cudaMemsetAsync(cnt, 0, n * sizeof(int), st);
    count_k<<<(E + 255) / 256, 256, 0, st>>>(head, E, cnt);
    int nb = (n + 1023) / 1024;
    scan_block_k<<<nb, 1024, 0, st>>>(cnt, n, offs, bsums);
    scan_final_k<<<1, 32, 0, st>>>(bsums, nb, offs, n, E);
    add_offs_k<<<nb, 1024, 0, st>>>(offs, cursor, bsums, n);
}

extern "C" void kernel_launch(void* const* d_in, const int* in_sizes, int n_in,
                              void* d_out, int out_size) {
    const float* user_emb         = (const float*)d_in[0];
    const float* entity_emb       = (const float*)d_in[1];
    const float* weight           = (const float*)d_in[2];
    const float* extra_weight     = (const float*)d_in[3];
    const float* interact_vals    = (const float*)d_in[4];
    const int*   edge_index       = (const int*)d_in[5];
    const int*   edge_type        = (const int*)d_in[6];
    const int*   extra_edge_index = (const int*)d_in[7];
    const int*   extra_edge_type  = (const int*)d_in[8];
    const int*   interact_idx     = (const int*)d_in[9];
    float* out = (float*)d_out;

    const int* kg_head = edge_index;
    const int* kg_tail = edge_index + E_KG;
    const int* pf_head = extra_edge_index;
    const int* pf_tail = extra_edge_index + E_PREF;
    const int* it_rows = interact_idx;
    const int* it_cols = interact_idx + NNZ;

    static cudaStream_t sA = nullptr, sB = nullptr;
    static cudaEvent_t evFork, evKG0, evIT0, evPref;
    if (!sA) {
        cudaStreamCreateWithFlags(&sA, cudaStreamNonBlocking);
        cudaStreamCreateWithFlags(&sB, cudaStreamNonBlocking);
        cudaEventCreateWithFlags(&evFork, cudaEventDisableTiming);
        cudaEventCreateWithFlags(&evKG0,  cudaEventDisableTiming);
        cudaEventCreateWithFlags(&evIT0,  cudaEventDisableTiming);
        cudaEventCreateWithFlags(&evPref, cudaEventDisableTiming);
    }

    float *ent_b, *usr_b, *usr_x, *fent_a, *fent_b;
    int *cnt_kg, *cnt_pf, *cnt_it, *bs_kg, *bs_pf, *bs_it;
    int *offs_kg, *offs_pf, *offs_it, *cur_kg, *cur_pf, *cur_it;
    int2 *ekg, *epf, *eit;
    cudaGetSymbolAddress((void**)&ent_b,   g_ent_b);
    cudaGetSymbolAddress((void**)&usr_b,   g_usr_b);
    cudaGetSymbolAddress((void**)&usr_x,   g_usr_x);
    cudaGetSymbolAddress((void**)&fent_a,  g_fent_a);
    cudaGetSymbolAddress((void**)&fent_b,  g_fent_b);
    cudaGetSymbolAddress((void**)&cnt_kg,  g_cnt_kg);
    cudaGetSymbolAddress((void**)&cnt_pf,  g_cnt_pf);
    cudaGetSymbolAddress((void**)&cnt_it,  g_cnt_it);
    cudaGetSymbolAddress((void**)&bs_kg,   g_bs_kg);
    cudaGetSymbolAddress((void**)&bs_pf,   g_bs_pf);
    cudaGetSymbolAddress((void**)&bs_it,   g_bs_it);
    cudaGetSymbolAddress((void**)&offs_kg, g_offs_kg);
    cudaGetSymbolAddress((void**)&offs_pf, g_offs_pf);
    cudaGetSymbolAddress((void**)&offs_it, g_offs_it);
    cudaGetSymbolAddress((void**)&cur_kg,  g_cur_kg);
    cudaGetSymbolAddress((void**)&cur_pf,  g_cur_pf);
    cudaGetSymbolAddress((void**)&cur_it,  g_cur_it);
    cudaGetSymbolAddress((void**)&ekg,     g_ekg);
    cudaGetSymbolAddress((void**)&epf,     g_epf);
    cudaGetSymbolAddress((void**)&eit,     g_eit);

    float* out_user = out;                        // user_res
    float* out_ent  = out + (size_t)N_USERS * D;  // final normalized entity_emb
    float* out_node = out + (size_t)N_NODES * D;  // node_res

    const int GB_ENT  = (N_ENTITIES * 16 + 255) / 256;
    const int GB_NODE = (N_NODES    * 16 + 255) / 256;
    const int GB_USER = (N_USERS    * 16 + 255) / 256;

    // ---- fork ----
    cudaEventRecord(evFork, 0);
    cudaStreamWaitEvent(sA, evFork, 0);
    cudaStreamWaitEvent(sB, evFork, 0);

    // ---- stream B: interact CSR, then it0 (after kg0) ----
    build_csr(sB, it_rows, NNZ, N_USERS, offs_it, cur_it, cnt_it, bs_it);
    fill_it_k<<<(NNZ + 255) / 256, 256, 0, sB>>>(it_rows, it_cols, interact_vals,
                                                 cur_it, eit);

    // ---- stream A: pref CSR, then pref0 (inputs only) ----
    build_csr(sA, pf_head, E_PREF, N_NODES, offs_pf, cur_pf, cnt_pf, bs_pf);
    fill_edges_k<<<(E_PREF + 255) / 256, 256, 0, sA>>>(pf_head, pf_tail, extra_edge_type,
                                                       E_PREF, 0, cur_pf, epf);
    gather_pref<<<GB_NODE, 256, 0, sA>>>(user_emb, entity_emb, extra_weight,
                                         offs_pf, epf, usr_b, out_node,
                                         user_emb, entity_emb, 0);

    // ---- main: kg chain ----
    build_csr(0, kg_head, E_KG, N_ENTITIES, offs_kg, cur_kg, cnt_kg, bs_kg);
    fill_edges_k<<<(E_KG + 255) / 256, 256, 0, 0>>>(kg_head, kg_tail, edge_type,
                                                    E_KG, 1, cur_kg, ekg);

    // hop 0: entity agg (reads input directly)
    gather_kg<<<GB_ENT, 256, 0, 0>>>(entity_emb, weight, offs_kg, ekg, ent_b, fent_a);
    cudaEventRecord(evKG0, 0);

    // hop 0 interact on stream B (parallel with kg1)
    cudaStreamWaitEvent(sB, evKG0, 0);
    gather_it<<<GB_USER, 256, 0, sB>>>(ent_b, fent_a, offs_it, eit,
                                       out_user, user_emb, 0);
    cudaEventRecord(evIT0, sB);

    // hop 1 pref on stream A (needs ent_b)
    cudaStreamWaitEvent(sA, evKG0, 0);
    gather_pref<<<GB_NODE, 256, 0, sA>>>(usr_b, ent_b, extra_weight,
                                         offs_pf, epf, usr_x, out_node,
                                         user_emb, entity_emb, 1);
    cudaEventRecord(evPref, sA);

    // hop 1: entity agg -> out_ent (main)
    gather_kg<<<GB_ENT, 256, 0, 0>>>(ent_b, weight, offs_kg, ekg, out_ent, fent_b);

    // hop 1 interact (main; after it0 finished accumulating out_user)
    cudaStreamWaitEvent(0, evIT0, 0);
    gather_it<<<GB_USER, 256, 0, 0>>>(out_ent, fent_b, offs_it, eit,
                                      out_user, user_emb, 1);

    // ---- join ----
    cudaStreamWaitEvent(0, evPref, 0);
}

// round 5
// speedup vs baseline: 2.5188x; 1.1575x over previous
#include <cuda_runtime.h>
#include <cuda_fp16.h>
#include <cstdint>

#define N_USERS    100000
#define N_ENTITIES 100000
#define N_NODES    200000
#define D          64
#define E_KG       1500000
#define E_PREF     1500000
#define NNZ        1000000

// ---------------- scratch (no device allocation allowed) ----------------
__device__ __half g_ent16_in[(size_t)N_ENTITIES * D];  // fp16 copy of entity_emb
__device__ __half g_usr16_in[(size_t)N_USERS * D];     // fp16 copy of user_emb
__device__ __half g_ent_b16 [(size_t)N_ENTITIES * D];  // hop-0 normalized entity
__device__ __half g_ent_c16 [(size_t)N_ENTITIES * D];  // hop-1 normalized entity
__device__ __half g_usr_b16 [(size_t)N_USERS * D];     // hop-0 node user-half
__device__ float  g_fent_a[N_ENTITIES];                // ||acc||/deg hop 0
__device__ float  g_fent_b[N_ENTITIES];                // ||acc||/deg hop 1

__device__ int g_cnt_kg[N_ENTITIES];
__device__ int g_cnt_pf[N_NODES];
__device__ int g_cnt_it[N_USERS];
__device__ int g_bs_kg[1024];
__device__ int g_bs_pf[1024];
__device__ int g_bs_it[1024];
__device__ int g_offs_kg[N_ENTITIES + 1];
__device__ int g_offs_pf[N_NODES + 1];
__device__ int g_offs_it[N_USERS + 1];
__device__ int g_cur_kg[N_ENTITIES];
__device__ int g_cur_pf[N_NODES];
__device__ int g_cur_it[N_USERS];
__device__ unsigned g_ekg[E_KG];    // tail | (type-1)<<18
__device__ unsigned g_epf[E_PREF];  // tail | type<<18
__device__ int2     g_eit[NNZ];     // (col, float_bits(val))

// ---------------- CSR build ----------------

__global__ void count_k(const int* __restrict__ head, int E, int* __restrict__ cnt) {
    int i = blockIdx.x * blockDim.x + threadIdx.x;
    if (i < E) atomicAdd(&cnt[head[i]], 1);
}

__global__ void scan_block_k(const int* __restrict__ cnt, int n,
                             int* __restrict__ offs, int* __restrict__ bsums) {
    __shared__ int sh[1024];
    int idx = blockIdx.x * 1024 + threadIdx.x;
    int v = (idx < n) ? cnt[idx] : 0;
    sh[threadIdx.x] = v;
    __syncthreads();
    #pragma unroll
    for (int off = 1; off < 1024; off <<= 1) {
        int t = (threadIdx.x >= off) ? sh[threadIdx.x - off] : 0;
        __syncthreads();
        sh[threadIdx.x] += t;
        __syncthreads();
    }
    if (idx < n) offs[idx] = sh[threadIdx.x] - v;
    if (threadIdx.x == 1023) bsums[blockIdx.x] = sh[1023];
}

__global__ void scan_final_k(int* __restrict__ bsums, int nb, int* __restrict__ offs,
                             int n, int total) {
    if (threadIdx.x == 0 && blockIdx.x == 0) {
        int run = 0;
        for (int b = 0; b < nb; b++) { int t = bsums[b]; bsums[b] = run; run += t; }
        offs[n] = total;
    }
}

__global__ void add_offs_k(int* __restrict__ offs, int* __restrict__ cursor,
                           const int* __restrict__ bsums, int n) {
    int idx = blockIdx.x * 1024 + threadIdx.x;
    if (idx < n) {
        int v = offs[idx] + bsums[blockIdx.x];
        offs[idx] = v;
        cursor[idx] = v;
    }
}

__global__ void fill_packed_k(const int* __restrict__ head, const int* __restrict__ tail,
                              const int* __restrict__ type, int E, int typeBias,
                              int* __restrict__ cursor, unsigned* __restrict__ out) {
    int e = blockIdx.x * blockDim.x + threadIdx.x;
    if (e >= E) return;
    int p = atomicAdd(&cursor[head[e]], 1);
    out[p] = (unsigned)tail[e] | ((unsigned)(type[e] - typeBias) << 18);
}

__global__ void fill_it_k(const int* __restrict__ rows, const int* __restrict__ cols,
                          const float* __restrict__ vals,
                          int* __restrict__ cursor, int2* __restrict__ out) {
    int e = blockIdx.x * blockDim.x + threadIdx.x;
    if (e >= NNZ) return;
    int p = atomicAdd(&cursor[rows[e]], 1);
    out[p] = make_int2(cols[e], __float_as_int(vals[e]));
}

// ---------------- fp32 -> fp16 conversion ----------------

__global__ void conv16_k(const float* __restrict__ src, __half* __restrict__ dst, int n4) {
    int i = blockIdx.x * blockDim.x + threadIdx.x;
    if (i >= n4) return;
    float4 v = __ldg((const float4*)src + i);
    __half2 a = __floats2half2_rn(v.x, v.y);
    __half2 b = __floats2half2_rn(v.z, v.w);
    uint2 u;
    u.x = *reinterpret_cast<unsigned*>(&a);
    u.y = *reinterpret_cast<unsigned*>(&b);
    ((uint2*)dst)[i] = u;
}

// ---------- gathers: 8 lanes / row, 8 halves (16B) / lane ----------

__device__ __forceinline__ void accum_h(float* acc, uint4 h, float4 wa, float4 wb) {
    float2 f0 = __half22float2(*reinterpret_cast<__half2*>(&h.x));
    float2 f1 = __half22float2(*reinterpret_cast<__half2*>(&h.y));
    float2 f2 = __half22float2(*reinterpret_cast<__half2*>(&h.z));
    float2 f3 = __half22float2(*reinterpret_cast<__half2*>(&h.w));
    acc[0] += f0.x * wa.x; acc[1] += f0.y * wa.y;
    acc[2] += f1.x * wa.z; acc[3] += f1.y * wa.w;
    acc[4] += f2.x * wb.x; acc[5] += f2.y * wb.y;
    acc[6] += f3.x * wb.z; acc[7] += f3.y * wb.w;
}

__device__ __forceinline__ void accum_hs(float* acc, uint4 h, float v) {
    float2 f0 = __half22float2(*reinterpret_cast<__half2*>(&h.x));
    float2 f1 = __half22float2(*reinterpret_cast<__half2*>(&h.y));
    float2 f2 = __half22float2(*reinterpret_cast<__half2*>(&h.z));
    float2 f3 = __half22float2(*reinterpret_cast<__half2*>(&h.w));
    acc[0] += f0.x * v; acc[1] += f0.y * v;
    acc[2] += f1.x * v; acc[3] += f1.y * v;
    acc[4] += f2.x * v; acc[5] += f2.y * v;
    acc[6] += f3.x * v; acc[7] += f3.y * v;
}

__device__ __forceinline__ float group_sumsq8(const float* a) {
    float ss = 0.f;
    #pragma unroll
    for (int k = 0; k < 8; k++) ss += a[k] * a[k];
    ss += __shfl_xor_sync(0xffffffffu, ss, 1);
    ss += __shfl_xor_sync(0xffffffffu, ss, 2);
    ss += __shfl_xor_sync(0xffffffffu, ss, 4);
    return ss;
}

__device__ __forceinline__ uint4 pack8(const float* r, float sc) {
    __half2 a = __floats2half2_rn(r[0] * sc, r[1] * sc);
    __half2 b = __floats2half2_rn(r[2] * sc, r[3] * sc);
    __half2 c = __floats2half2_rn(r[4] * sc, r[5] * sc);
    __half2 d = __floats2half2_rn(r[6] * sc, r[7] * sc);
    uint4 u;
    u.x = *reinterpret_cast<unsigned*>(&a);
    u.y = *reinterpret_cast<unsigned*>(&b);
    u.z = *reinterpret_cast<unsigned*>(&c);
    u.w = *reinterpret_cast<unsigned*>(&d);
    return u;
}

// entity agg: acc = sum(ent16[tail] * weight[type]); out16 = l2norm(acc) (fp16);
// out32 (optional) = l2norm(acc) fp32; f_out = ||acc||/max(deg,1)
__global__ void __launch_bounds__(256)
gather_kg_h(const __half* __restrict__ ent16, const float* __restrict__ weight,
            const int* __restrict__ offs, const unsigned* __restrict__ edges,
            __half* __restrict__ out16, float* __restrict__ out32,
            float* __restrict__ f_out) {
    int t = blockIdx.x * blockDim.x + threadIdx.x;
    int w = t >> 3, ln = t & 7;
    if (w >= N_ENTITIES) return;
    int s = __ldg(&offs[w]), e = __ldg(&offs[w + 1]);
    float acc[8] = {0, 0, 0, 0, 0, 0, 0, 0};
    int i = s;
    for (; i + 1 < e; i += 2) {
        unsigned p0 = __ldg(&edges[i]);
        unsigned p1 = __ldg(&edges[i + 1]);
        int t0 = p0 & 0x3FFFF, y0 = p0 >> 18;
        int t1 = p1 & 0x3FFFF, y1 = p1 >> 18;
        uint4 h0 = __ldg((const uint4*)(ent16 + (size_t)t0 * D) + ln);
        uint4 h1 = __ldg((const uint4*)(ent16 + (size_t)t1 * D) + ln);
        const float4* w0p = (const float4*)(weight + (size_t)y0 * D) + ln * 2;
        const float4* w1p = (const float4*)(weight + (size_t)y1 * D) + ln * 2;
        float4 wa0 = __ldg(w0p), wb0 = __ldg(w0p + 1);
        float4 wa1 = __ldg(w1p), wb1 = __ldg(w1p + 1);
        accum_h(acc, h0, wa0, wb0);
        accum_h(acc, h1, wa1, wb1);
    }
    if (i < e) {
        unsigned p0 = __ldg(&edges[i]);
        int t0 = p0 & 0x3FFFF, y0 = p0 >> 18;
        uint4 h0 = __ldg((const uint4*)(ent16 + (size_t)t0 * D) + ln);
        const float4* w0p = (const float4*)(weight + (size_t)y0 * D) + ln * 2;
        accum_h(acc, h0, __ldg(w0p), __ldg(w0p + 1));
    }
    float nrm = fmaxf(sqrtf(group_sumsq8(acc)), 1e-12f);
    float sc = 1.0f / nrm;
    ((uint4*)(out16 + (size_t)w * D))[ln] = pack8(acc, sc);
    if (out32) {
        float4* o = (float4*)(out32 + (size_t)w * D) + ln * 2;
        o[0] = make_float4(acc[0] * sc, acc[1] * sc, acc[2] * sc, acc[3] * sc);
        o[1] = make_float4(acc[4] * sc, acc[5] * sc, acc[6] * sc, acc[7] * sc);
    }
    if (ln == 0) f_out[w] = nrm / fmaxf((float)(e - s), 1.0f);
}

// node agg: r = l2norm(sum(all16[tail] * eweight[type]))
// mode 0: out_node = r; usr_next16 = r (w < N_USERS)
// mode 1: out_node += init + r   (init = concat(user0, ent0) fp32)
__global__ void __launch_bounds__(256)
gather_pref_h(const __half* __restrict__ usr16, const __half* __restrict__ ent16,
              const float* __restrict__ eweight,
              const int* __restrict__ offs, const unsigned* __restrict__ edges,
              __half* __restrict__ usr_next16, float* __restrict__ out_node,
              const float* __restrict__ user0, const float* __restrict__ ent0,
              int mode) {
    int t = blockIdx.x * blockDim.x + threadIdx.x;
    int w = t >> 3, ln = t & 7;
    if (w >= N_NODES) return;
    int s = __ldg(&offs[w]), e = __ldg(&offs[w + 1]);
    float acc[8] = {0, 0, 0, 0, 0, 0, 0, 0};
    int i = s;
    for (; i + 1 < e; i += 2) {
        unsigned p0 = __ldg(&edges[i]);
        unsigned p1 = __ldg(&edges[i + 1]);
        int t0 = p0 & 0x3FFFF, y0 = p0 >> 18;
        int t1 = p1 & 0x3FFFF, y1 = p1 >> 18;
        const __half* s0 = (t0 < N_USERS) ? (usr16 + (size_t)t0 * D)
                                          : (ent16 + (size_t)(t0 - N_USERS) * D);
        const __half* s1 = (t1 < N_USERS) ? (usr16 + (size_t)t1 * D)
                                          : (ent16 + (size_t)(t1 - N_USERS) * D);
        uint4 h0 = __ldg((const uint4*)s0 + ln);
        uint4 h1 = __ldg((const uint4*)s1 + ln);
        const float4* w0p = (const float4*)(eweight + (size_t)y0 * D) + ln * 2;
        const float4* w1p = (const float4*)(eweight + (size_t)y1 * D) + ln * 2;
        float4 wa0 = __ldg(w0p), wb0 = __ldg(w0p + 1);
        float4 wa1 = __ldg(w1p), wb1 = __ldg(w1p + 1);
        accum_h(acc, h0, wa0, wb0);
        accum_h(acc, h1, wa1, wb1);
    }
    if (i < e) {
        unsigned p0 = __ldg(&edges[i]);
        int t0 = p0 & 0x3FFFF, y0 = p0 >> 18;
        const __half* s0 = (t0 < N_USERS) ? (usr16 + (size_t)t0 * D)
                                          : (ent16 + (size_t)(t0 - N_USERS) * D);
        uint4 h0 = __ldg((const uint4*)s0 + ln);
        const float4* w0p = (const float4*)(eweight + (size_t)y0 * D) + ln * 2;
        accum_h(acc, h0, __ldg(w0p), __ldg(w0p + 1));
    }
    float sc = 1.0f / fmaxf(sqrtf(group_sumsq8(acc)), 1e-12f);
    float4 r0 = make_float4(acc[0] * sc, acc[1] * sc, acc[2] * sc, acc[3] * sc);
    float4 r1 = make_float4(acc[4] * sc, acc[5] * sc, acc[6] * sc, acc[7] * sc);
    float4* o = (float4*)(out_node + (size_t)w * D) + ln * 2;
    if (mode == 0) {
        if (w < N_USERS)
            ((uint4*)(usr_next16 + (size_t)w * D))[ln] = pack8(acc, sc);
        o[0] = r0;
        o[1] = r1;
    } else {
        const float* ip = (w < N_USERS) ? (user0 + (size_t)w * D)
                                        : (ent0 + (size_t)(w - N_USERS) * D);
        const float4* iv = (const float4*)ip + ln * 2;
        float4 i0 = __ldg(iv), i1 = __ldg(iv + 1);
        float4 a0 = o[0], a1 = o[1];
        o[0] = make_float4(a0.x + i0.x + r0.x, a0.y + i0.y + r0.y,
                           a0.z + i0.z + r0.z, a0.w + i0.w + r0.w);
        o[1] = make_float4(a1.x + i1.x + r1.x, a1.y + i1.y + r1.y,
                           a1.z + i1.z + r1.z, a1.w + i1.w + r1.w);
    }
}

// user: r = l2norm(sum(val * f[col] * ent16[col]))
// mode 0: out_user = user0 + r ; mode 1: out_user += r
__global__ void __launch_bounds__(256)
gather_it_h(const __half* __restrict__ ent16, const float* __restrict__ f,
            const int* __restrict__ offs, const int2* __restrict__ edges,
            float* __restrict__ out_user, const float* __restrict__ user0, int mode) {
    int t = blockIdx.x * blockDim.x + threadIdx.x;
    int w = t >> 3, ln = t & 7;
    if (w >= N_USERS) return;
    int s = __ldg(&offs[w]), e = __ldg(&offs[w + 1]);
    float acc[8] = {0, 0, 0, 0, 0, 0, 0, 0};
    int i = s;
    for (; i + 1 < e; i += 2) {
        int2 e0 = __ldg(&edges[i]);
        int2 e1 = __ldg(&edges[i + 1]);
        float v0 = __int_as_float(e0.y) * __ldg(&f[e0.x]);
        float v1 = __int_as_float(e1.y) * __ldg(&f[e1.x]);
        uint4 h0 = __ldg((const uint4*)(ent16 + (size_t)e0.x * D) + ln);
        uint4 h1 = __ldg((const uint4*)(ent16 + (size_t)e1.x * D) + ln);
        accum_hs(acc, h0, v0);
        accum_hs(acc, h1, v1);
    }
    if (i < e) {
        int2 e0 = __ldg(&edges[i]);
        float v0 = __int_as_float(e0.y) * __ldg(&f[e0.x]);
        uint4 h0 = __ldg((const uint4*)(ent16 + (size_t)e0.x * D) + ln);
        accum_hs(acc, h0, v0);
    }
    float sc = 1.0f / fmaxf(sqrtf(group_sumsq8(acc)), 1e-12f);
    float4* o = (float4*)(out_user + (size_t)w * D) + ln * 2;
    if (mode == 0) {
        const float4* up = (const float4*)(user0 + (size_t)w * D) + ln * 2;
        float4 u0 = __ldg(up), u1 = __ldg(up + 1);
        o[0] = make_float4(u0.x + acc[0] * sc, u0.y + acc[1] * sc,
                           u0.z + acc[2] * sc, u0.w + acc[3] * sc);
        o[1] = make_float4(u1.x + acc[4] * sc, u1.y + acc[5] * sc,
                           u1.z + acc[6] * sc, u1.w + acc[7] * sc);
    } else {
        float4 a0 = o[0], a1 = o[1];
        o[0] = make_float4(a0.x + acc[0] * sc, a0.y + acc[1] * sc,
                           a0.z + acc[2] * sc, a0.w + acc[3] * sc);
        o[1] = make_float4(a1.x + acc[4] * sc, a1.y + acc[5] * sc,
                           a1.z + acc[6] * sc, a1.w + acc[7] * sc);
    }
}

// ---------------- launch ----------------

static void build_csr(cudaStream_t st, const int* head, int E, int n,
                      int* offs, int* cursor, int* cnt, int* bsums) {
    cudaMemsetAsync(cnt, 0, n * sizeof(int), st);
    count_k<<<(E + 255) / 256, 256, 0, st>>>(head, E, cnt);
    int nb = (n + 1023) / 1024;
    scan_block_k<<<nb, 1024, 0, st>>>(cnt, n, offs, bsums);
    scan_final_k<<<1, 32, 0, st>>>(bsums, nb, offs, n, E);
    add_offs_k<<<nb, 1024, 0, st>>>(offs, cursor, bsums, n);
}

extern "C" void kernel_launch(void* const* d_in, const int* in_sizes, int n_in,
                              void* d_out, int out_size) {
    const float* user_emb         = (const float*)d_in[0];
    const float* entity_emb       = (const float*)d_in[1];
    const float* weight           = (const float*)d_in[2];
    const float* extra_weight     = (const float*)d_in[3];
    const float* interact_vals    = (const float*)d_in[4];
    const int*   edge_index       = (const int*)d_in[5];
    const int*   edge_type        = (const int*)d_in[6];
    const int*   extra_edge_index = (const int*)d_in[7];
    const int*   extra_edge_type  = (const int*)d_in[8];
    const int*   interact_idx     = (const int*)d_in[9];
    float* out = (float*)d_out;

    const int* kg_head = edge_index;
    const int* kg_tail = edge_index + E_KG;
    const int* pf_head = extra_edge_index;
    const int* pf_tail = extra_edge_index + E_PREF;
    const int* it_rows = interact_idx;
    const int* it_cols = interact_idx + NNZ;

    static cudaStream_t sA = nullptr, sB = nullptr;
    static cudaEvent_t evFork, evCE, evKG0, evIT0, evPref;
    if (!sA) {
        cudaStreamCreateWithFlags(&sA, cudaStreamNonBlocking);
        cudaStreamCreateWithFlags(&sB, cudaStreamNonBlocking);
        cudaEventCreateWithFlags(&evFork, cudaEventDisableTiming);
        cudaEventCreateWithFlags(&evCE,   cudaEventDisableTiming);
        cudaEventCreateWithFlags(&evKG0,  cudaEventDisableTiming);
        cudaEventCreateWithFlags(&evIT0,  cudaEventDisableTiming);
        cudaEventCreateWithFlags(&evPref, cudaEventDisableTiming);
    }

    __half *ent16_in, *usr16_in, *ent_b16, *ent_c16, *usr_b16;
    float *fent_a, *fent_b;
    int *cnt_kg, *cnt_pf, *cnt_it, *bs_kg, *bs_pf, *bs_it;
    int *offs_kg, *offs_pf, *offs_it, *cur_kg, *cur_pf, *cur_it;
    unsigned *ekg, *epf;
    int2 *eit;
    cudaGetSymbolAddress((void**)&ent16_in, g_ent16_in);
    cudaGetSymbolAddress((void**)&usr16_in, g_usr16_in);
    cudaGetSymbolAddress((void**)&ent_b16,  g_ent_b16);
    cudaGetSymbolAddress((void**)&ent_c16,  g_ent_c16);
    cudaGetSymbolAddress((void**)&usr_b16,  g_usr_b16);
    cudaGetSymbolAddress((void**)&fent_a,   g_fent_a);
    cudaGetSymbolAddress((void**)&fent_b,   g_fent_b);
    cudaGetSymbolAddress((void**)&cnt_kg,   g_cnt_kg);
    cudaGetSymbolAddress((void**)&cnt_pf,   g_cnt_pf);
    cudaGetSymbolAddress((void**)&cnt_it,   g_cnt_it);
    cudaGetSymbolAddress((void**)&bs_kg,    g_bs_kg);
    cudaGetSymbolAddress((void**)&bs_pf,    g_bs_pf);
    cudaGetSymbolAddress((void**)&bs_it,    g_bs_it);
    cudaGetSymbolAddress((void**)&offs_kg,  g_offs_kg);
    cudaGetSymbolAddress((void**)&offs_pf,  g_offs_pf);
    cudaGetSymbolAddress((void**)&offs_it,  g_offs_it);
    cudaGetSymbolAddress((void**)&cur_kg,   g_cur_kg);
    cudaGetSymbolAddress((void**)&cur_pf,   g_cur_pf);
    cudaGetSymbolAddress((void**)&cur_it,   g_cur_it);
    cudaGetSymbolAddress((void**)&ekg,      g_ekg);
    cudaGetSymbolAddress((void**)&epf,      g_epf);
    cudaGetSymbolAddress((void**)&eit,      g_eit);

    float* out_user = out;                        // user_res
    float* out_ent  = out + (size_t)N_USERS * D;  // final normalized entity_emb (fp32)
    float* out_node = out + (size_t)N_NODES * D;  // node_res

    const int GB_ENT  = (N_ENTITIES * 8 + 255) / 256;
    const int GB_NODE = (N_NODES    * 8 + 255) / 256;
    const int GB_USER = (N_USERS    * 8 + 255) / 256;
    const int CV_ENT  = (N_ENTITIES * D / 4 + 255) / 256;
    const int CV_USR  = (N_USERS    * D / 4 + 255) / 256;

    // ---- fork ----
    cudaEventRecord(evFork, 0);
    cudaStreamWaitEvent(sA, evFork, 0);
    cudaStreamWaitEvent(sB, evFork, 0);

    // ---- main: convert entity table to fp16 first (kg0 + pref0 need it) ----
    conv16_k<<<CV_ENT, 256, 0, 0>>>(entity_emb, ent16_in, N_ENTITIES * D / 4);
    cudaEventRecord(evCE, 0);

    // ---- stream B: interact CSR ----
    build_csr(sB, it_rows, NNZ, N_USERS, offs_it, cur_it, cnt_it, bs_it);
    fill_it_k<<<(NNZ + 255) / 256, 256, 0, sB>>>(it_rows, it_cols, interact_vals,
                                                 cur_it, eit);

    // ---- stream A: user conversion + pref CSR + pref0 ----
    conv16_k<<<CV_USR, 256, 0, sA>>>(user_emb, usr16_in, N_USERS * D / 4);
    build_csr(sA, pf_head, E_PREF, N_NODES, offs_pf, cur_pf, cnt_pf, bs_pf);
    fill_packed_k<<<(E_PREF + 255) / 256, 256, 0, sA>>>(pf_head, pf_tail, extra_edge_type,
                                                        E_PREF, 0, cur_pf, epf);
    cudaStreamWaitEvent(sA, evCE, 0);
    gather_pref_h<<<GB_NODE, 256, 0, sA>>>(usr16_in, ent16_in, extra_weight,
                                           offs_pf, epf, usr_b16, out_node,
                                           user_emb, entity_emb, 0);

    // ---- main: kg chain ----
    build_csr(0, kg_head, E_KG, N_ENTITIES, offs_kg, cur_kg, cnt_kg, bs_kg);
    fill_packed_k<<<(E_KG + 255) / 256, 256, 0, 0>>>(kg_head, kg_tail, edge_type,
                                                     E_KG, 1, cur_kg, ekg);

    // hop 0: entity agg (fp16 source, fp16 out only)
    gather_kg_h<<<GB_ENT, 256, 0, 0>>>(ent16_in, weight, offs_kg, ekg,
                                       ent_b16, nullptr, fent_a);
    cudaEventRecord(evKG0, 0);

    // hop 0 interact on stream B (parallel with kg1)
    cudaStreamWaitEvent(sB, evKG0, 0);
    gather_it_h<<<GB_USER, 256, 0, sB>>>(ent_b16, fent_a, offs_it, eit,
                                         out_user, user_emb, 0);
    cudaEventRecord(evIT0, sB);

    // hop 1 pref on stream A
    cudaStreamWaitEvent(sA, evKG0, 0);
    gather_pref_h<<<GB_NODE, 256, 0, sA>>>(usr_b16, ent_b16, extra_weight,
                                           offs_pf, epf, nullptr, out_node,
                                           user_emb, entity_emb, 1);
    cudaEventRecord(evPref, sA);

    // hop 1: entity agg -> out_ent (fp32) + ent_c16 (fp16 for it1)
    gather_kg_h<<<GB_ENT, 256, 0, 0>>>(ent_b16, weight, offs_kg, ekg,
                                       ent_c16, out_ent, fent_b);

    // hop 1 interact (main; after it0)
    cudaStreamWaitEvent(0, evIT0, 0);
    gather_it_h<<<GB_USER, 256, 0, 0>>>(ent_c16, fent_b, offs_it, eit,
                                        out_user, user_emb, 1);

    // ---- join ----
    cudaStreamWaitEvent(0, evPref, 0);
}

// round 6
// speedup vs baseline: 2.8797x; 1.1433x over previous
#include <cuda_runtime.h>
#include <cuda_fp16.h>
#include <cstdint>

#define N_USERS    100000
#define N_ENTITIES 100000
#define N_NODES    200000
#define D          64
#define E_KG       1500000
#define E_PREF     1500000
#define NNZ        1000000

// ---------------- scratch (no device allocation allowed) ----------------
__device__ __half g_ent16_in[(size_t)N_ENTITIES * D];
__device__ __half g_usr16_in[(size_t)N_USERS * D];
__device__ __half g_ent_b16 [(size_t)N_ENTITIES * D];
__device__ __half g_ent_c16 [(size_t)N_ENTITIES * D];
__device__ __half g_usr_b16 [(size_t)N_USERS * D];
__device__ __half g_w16 [16 * D];   // kg weight fp16
__device__ __half g_ew16[32 * D];   // pref weight fp16
__device__ float  g_fent_a[N_ENTITIES];
__device__ float  g_fent_b[N_ENTITIES];

__device__ int g_cnt_kg[N_ENTITIES];
__device__ int g_cnt_pf[N_NODES];
__device__ int g_cnt_it[N_USERS];
__device__ int g_bs_kg[1024];
__device__ int g_bs_pf[1024];
__device__ int g_bs_it[1024];
__device__ int g_offs_kg[N_ENTITIES + 1];
__device__ int g_offs_pf[N_NODES + 1];
__device__ int g_offs_it[N_USERS + 1];
__device__ int g_cur_kg[N_ENTITIES];
__device__ int g_cur_pf[N_NODES];
__device__ int g_cur_it[N_USERS];
__device__ unsigned g_ekg[E_KG];    // tail | (type-1)<<18
__device__ unsigned g_epf[E_PREF];  // tail | type<<18
__device__ int2     g_eit[NNZ];     // (col, float_bits(val))

// ---------------- CSR build ----------------

__global__ void count_k(const int* __restrict__ head, int E, int* __restrict__ cnt) {
    int i = blockIdx.x * blockDim.x + threadIdx.x;
    if (i < E) atomicAdd(&cnt[head[i]], 1);
}

__global__ void scan_block_k(const int* __restrict__ cnt, int n,
                             int* __restrict__ offs, int* __restrict__ bsums) {
    __shared__ int sh[1024];
    int idx = blockIdx.x * 1024 + threadIdx.x;
    int v = (idx < n) ? cnt[idx] : 0;
    sh[threadIdx.x] = v;
    __syncthreads();
    #pragma unroll
    for (int off = 1; off < 1024; off <<= 1) {
        int t = (threadIdx.x >= off) ? sh[threadIdx.x - off] : 0;
        __syncthreads();
        sh[threadIdx.x] += t;
        __syncthreads();
    }
    if (idx < n) offs[idx] = sh[threadIdx.x] - v;
    if (threadIdx.x == 1023) bsums[blockIdx.x] = sh[1023];
}

// parallel exclusive scan of block sums (nb <= 256)
__global__ void scan_final_k(int* __restrict__ bsums, int nb, int* __restrict__ offs,
                             int n, int total) {
    __shared__ int sh[256];
    int v = ((int)threadIdx.x < nb) ? bsums[threadIdx.x] : 0;
    sh[threadIdx.x] = v;
    __syncthreads();
    #pragma unroll
    for (int off = 1; off < 256; off <<= 1) {
        int t = (threadIdx.x >= off) ? sh[threadIdx.x - off] : 0;
        __syncthreads();
        sh[threadIdx.x] += t;
        __syncthreads();
    }
    if ((int)threadIdx.x < nb) bsums[threadIdx.x] = sh[threadIdx.x] - v;
    if (threadIdx.x == 0) offs[n] = total;
}

__global__ void add_offs_k(int* __restrict__ offs, int* __restrict__ cursor,
                           const int* __restrict__ bsums, int n) {
    int idx = blockIdx.x * 1024 + threadIdx.x;
    if (idx < n) {
        int v = offs[idx] + bsums[blockIdx.x];
        offs[idx] = v;
        cursor[idx] = v;
    }
}

__global__ void fill_packed_k(const int* __restrict__ head, const int* __restrict__ tail,
                              const int* __restrict__ type, int E, int typeBias,
                              int* __restrict__ cursor, unsigned* __restrict__ out) {
    int e = blockIdx.x * blockDim.x + threadIdx.x;
    if (e >= E) return;
    int p = atomicAdd(&cursor[head[e]], 1);
    out[p] = (unsigned)tail[e] | ((unsigned)(type[e] - typeBias) << 18);
}

__global__ void fill_it_k(const int* __restrict__ rows, const int* __restrict__ cols,
                          const float* __restrict__ vals,
                          int* __restrict__ cursor, int2* __restrict__ out) {
    int e = blockIdx.x * blockDim.x + threadIdx.x;
    if (e >= NNZ) return;
    int p = atomicAdd(&cursor[rows[e]], 1);
    out[p] = make_int2(cols[e], __float_as_int(vals[e]));
}

// ---------------- fp32 -> fp16 conversion ----------------

__global__ void conv16_k(const float* __restrict__ src, __half* __restrict__ dst, int n4) {
    int i = blockIdx.x * blockDim.x + threadIdx.x;
    if (i >= n4) return;
    float4 v = __ldg((const float4*)src + i);
    __half2 a = __floats2half2_rn(v.x, v.y);
    __half2 b = __floats2half2_rn(v.z, v.w);
    uint2 u;
    u.x = *reinterpret_cast<unsigned*>(&a);
    u.y = *reinterpret_cast<unsigned*>(&b);
    ((uint2*)dst)[i] = u;
}

// ---------- gathers: 8 lanes / row, 8 halves (16B) / lane ----------

// accumulate fp16 x * fp16 w into fp32 acc (convert both, fp32 FMA)
__device__ __forceinline__ void accum_hh(float* acc, uint4 x, uint4 w) {
    float2 x0 = __half22float2(*reinterpret_cast<__half2*>(&x.x));
    float2 x1 = __half22float2(*reinterpret_cast<__half2*>(&x.y));
    float2 x2 = __half22float2(*reinterpret_cast<__half2*>(&x.z));
    float2 x3 = __half22float2(*reinterpret_cast<__half2*>(&x.w));
    float2 w0 = __half22float2(*reinterpret_cast<__half2*>(&w.x));
    float2 w1 = __half22float2(*reinterpret_cast<__half2*>(&w.y));
    float2 w2 = __half22float2(*reinterpret_cast<__half2*>(&w.z));
    float2 w3 = __half22float2(*reinterpret_cast<__half2*>(&w.w));
    acc[0] += x0.x * w0.x; acc[1] += x0.y * w0.y;
    acc[2] += x1.x * w1.x; acc[3] += x1.y * w1.y;
    acc[4] += x2.x * w2.x; acc[5] += x2.y * w2.y;
    acc[6] += x3.x * w3.x; acc[7] += x3.y * w3.y;
}

__device__ __forceinline__ void accum_hs(float* acc, uint4 h, float v) {
    float2 f0 = __half22float2(*reinterpret_cast<__half2*>(&h.x));
    float2 f1 = __half22float2(*reinterpret_cast<__half2*>(&h.y));
    float2 f2 = __half22float2(*reinterpret_cast<__half2*>(&h.z));
    float2 f3 = __half22float2(*reinterpret_cast<__half2*>(&h.w));
    acc[0] += f0.x * v; acc[1] += f0.y * v;
    acc[2] += f1.x * v; acc[3] += f1.y * v;
    acc[4] += f2.x * v; acc[5] += f2.y * v;
    acc[6] += f3.x * v; acc[7] += f3.y * v;
}

__device__ __forceinline__ float group_sumsq8(const float* a) {
    float ss = 0.f;
    #pragma unroll
    for (int k = 0; k < 8; k++) ss += a[k] * a[k];
    ss += __shfl_xor_sync(0xffffffffu, ss, 1);
    ss += __shfl_xor_sync(0xffffffffu, ss, 2);
    ss += __shfl_xor_sync(0xffffffffu, ss, 4);
    return ss;
}

__device__ __forceinline__ uint4 pack8(const float* r, float sc) {
    __half2 a = __floats2half2_rn(r[0] * sc, r[1] * sc);
    __half2 b = __floats2half2_rn(r[2] * sc, r[3] * sc);
    __half2 c = __floats2half2_rn(r[4] * sc, r[5] * sc);
    __half2 d = __floats2half2_rn(r[6] * sc, r[7] * sc);
    uint4 u;
    u.x = *reinterpret_cast<unsigned*>(&a);
    u.y = *reinterpret_cast<unsigned*>(&b);
    u.z = *reinterpret_cast<unsigned*>(&c);
    u.w = *reinterpret_cast<unsigned*>(&d);
    return u;
}

// entity agg: acc = sum(ent16[tail] * w16[type]); out16 = l2norm (fp16);
// out32 (optional) = l2norm fp32; f_out = ||acc||/max(deg,1)
__global__ void __launch_bounds__(256)
gather_kg_h(const __half* __restrict__ ent16, const __half* __restrict__ w16,
            const int* __restrict__ offs, const unsigned* __restrict__ edges,
            __half* __restrict__ out16, float* __restrict__ out32,
            float* __restrict__ f_out) {
    int t = blockIdx.x * blockDim.x + threadIdx.x;
    int w = t >> 3, ln = t & 7;
    if (w >= N_ENTITIES) return;
    int s = __ldg(&offs[w]), e = __ldg(&offs[w + 1]);
    float acc[8] = {0, 0, 0, 0, 0, 0, 0, 0};
    int i = s;
    for (; i + 3 < e; i += 4) {
        unsigned p0 = __ldg(&edges[i]);
        unsigned p1 = __ldg(&edges[i + 1]);
        unsigned p2 = __ldg(&edges[i + 2]);
        unsigned p3 = __ldg(&edges[i + 3]);
        uint4 h0 = __ldg((const uint4*)(ent16 + (size_t)(p0 & 0x3FFFF) * D) + ln);
        uint4 h1 = __ldg((const uint4*)(ent16 + (size_t)(p1 & 0x3FFFF) * D) + ln);
        uint4 h2 = __ldg((const uint4*)(ent16 + (size_t)(p2 & 0x3FFFF) * D) + ln);
        uint4 h3 = __ldg((const uint4*)(ent16 + (size_t)(p3 & 0x3FFFF) * D) + ln);
        uint4 w0 = __ldg((const uint4*)(w16 + (size_t)(p0 >> 18) * D) + ln);
        uint4 w1 = __ldg((const uint4*)(w16 + (size_t)(p1 >> 18) * D) + ln);
        uint4 w2 = __ldg((const uint4*)(w16 + (size_t)(p2 >> 18) * D) + ln);
        uint4 w3 = __ldg((const uint4*)(w16 + (size_t)(p3 >> 18) * D) + ln);
        accum_hh(acc, h0, w0); accum_hh(acc, h1, w1);
        accum_hh(acc, h2, w2); accum_hh(acc, h3, w3);
    }
    for (; i < e; i++) {
        unsigned p0 = __ldg(&edges[i]);
        uint4 h0 = __ldg((const uint4*)(ent16 + (size_t)(p0 & 0x3FFFF) * D) + ln);
        uint4 w0 = __ldg((const uint4*)(w16 + (size_t)(p0 >> 18) * D) + ln);
        accum_hh(acc, h0, w0);
    }
    float nrm = fmaxf(sqrtf(group_sumsq8(acc)), 1e-12f);
    float sc = 1.0f / nrm;
    ((uint4*)(out16 + (size_t)w * D))[ln] = pack8(acc, sc);
    if (out32) {
        float4* o = (float4*)(out32 + (size_t)w * D) + ln * 2;
        o[0] = make_float4(acc[0] * sc, acc[1] * sc, acc[2] * sc, acc[3] * sc);
        o[1] = make_float4(acc[4] * sc, acc[5] * sc, acc[6] * sc, acc[7] * sc);
    }
    if (ln == 0) f_out[w] = nrm / fmaxf((float)(e - s), 1.0f);
}

// node agg: r = l2norm(sum(all16[tail] * ew16[type]))
// mode 0: out_node = r; usr_next16 = r (w < N_USERS)
// mode 1: out_node += init + r
__global__ void __launch_bounds__(256)
gather_pref_h(const __half* __restrict__ usr16, const __half* __restrict__ ent16,
              const __half* __restrict__ ew16,
              const int* __restrict__ offs, const unsigned* __restrict__ edges,
              __half* __restrict__ usr_next16, float* __restrict__ out_node,
              const float* __restrict__ user0, const float* __restrict__ ent0,
              int mode) {
    int t = blockIdx.x * blockDim.x + threadIdx.x;
    int w = t >> 3, ln = t & 7;
    if (w >= N_NODES) return;
    int s = __ldg(&offs[w]), e = __ldg(&offs[w + 1]);
    float acc[8] = {0, 0, 0, 0, 0, 0, 0, 0};
    int i = s;
    for (; i + 3 < e; i += 4) {
        unsigned p0 = __ldg(&edges[i]);
        unsigned p1 = __ldg(&edges[i + 1]);
        unsigned p2 = __ldg(&edges[i + 2]);
        unsigned p3 = __ldg(&edges[i + 3]);
        int t0 = p0 & 0x3FFFF, t1 = p1 & 0x3FFFF, t2 = p2 & 0x3FFFF, t3 = p3 & 0x3FFFF;
        const __half* s0 = (t0 < N_USERS) ? (usr16 + (size_t)t0 * D)
                                          : (ent16 + (size_t)(t0 - N_USERS) * D);
        const __half* s1 = (t1 < N_USERS) ? (usr16 + (size_t)t1 * D)
                                          : (ent16 + (size_t)(t1 - N_USERS) * D);
        const __half* s2 = (t2 < N_USERS) ? (usr16 + (size_t)t2 * D)
                                          : (ent16 + (size_t)(t2 - N_USERS) * D);
        const __half* s3 = (t3 < N_USERS) ? (usr16 + (size_t)t3 * D)
                                          : (ent16 + (size_t)(t3 - N_USERS) * D);
        uint4 h0 = __ldg((const uint4*)s0 + ln);
        uint4 h1 = __ldg((const uint4*)s1 + ln);
        uint4 h2 = __ldg((const uint4*)s2 + ln);
        uint4 h3 = __ldg((const uint4*)s3 + ln);
        uint4 w0 = __ldg((const uint4*)(ew16 + (size_t)(p0 >> 18) * D) + ln);
        uint4 w1 = __ldg((const uint4*)(ew16 + (size_t)(p1 >> 18) * D) + ln);
        uint4 w2 = __ldg((const uint4*)(ew16 + (size_t)(p2 >> 18) * D) + ln);
        uint4 w3 = __ldg((const uint4*)(ew16 + (size_t)(p3 >> 18) * D) + ln);
        accum_hh(acc, h0, w0); accum_hh(acc, h1, w1);
        accum_hh(acc, h2, w2); accum_hh(acc, h3, w3);
    }
    for (; i < e; i++) {
        unsigned p0 = __ldg(&edges[i]);
        int t0 = p0 & 0x3FFFF;
        const __half* s0 = (t0 < N_USERS) ? (usr16 + (size_t)t0 * D)
                                          : (ent16 + (size_t)(t0 - N_USERS) * D);
        uint4 h0 = __ldg((const uint4*)s0 + ln);
        uint4 w0 = __ldg((const uint4*)(ew16 + (size_t)(p0 >> 18) * D) + ln);
        accum_hh(acc, h0, w0);
    }
    float sc = 1.0f / fmaxf(sqrtf(group_sumsq8(acc)), 1e-12f);
    float4 r0 = make_float4(acc[0] * sc, acc[1] * sc, acc[2] * sc, acc[3] * sc);
    float4 r1 = make_float4(acc[4] * sc, acc[5] * sc, acc[6] * sc, acc[7] * sc);
    float4* o = (float4*)(out_node + (size_t)w * D) + ln * 2;
    if (mode == 0) {
        if (w < N_USERS)
            ((uint4*)(usr_next16 + (size_t)w * D))[ln] = pack8(acc, sc);
        o[0] = r0;
        o[1] = r1;
    } else {
        const float* ip = (w < N_USERS) ? (user0 + (size_t)w * D)
                                        : (ent0 + (size_t)(w - N_USERS) * D);
        const float4* iv = (const float4*)ip + ln * 2;
        float4 i0 = __ldg(iv), i1 = __ldg(iv + 1);
        float4 a0 = o[0], a1 = o[1];
        o[0] = make_float4(a0.x + i0.x + r0.x, a0.y + i0.y + r0.y,
                           a0.z + i0.z + r0.z, a0.w + i0.w + r0.w);
        o[1] = make_float4(a1.x + i1.x + r1.x, a1.y + i1.y + r1.y,
                           a1.z + i1.z + r1.z, a1.w + i1.w + r1.w);
    }
}

// user: r = l2norm(sum(val * f[col] * ent16[col]))
// mode 0: out_user = user0 + r ; mode 1: out_user += r
__global__ void __launch_bounds__(256)
gather_it_h(const __half* __restrict__ ent16, const float* __restrict__ f,
            const int* __restrict__ offs, const int2* __restrict__ edges,
            float* __restrict__ out_user, const float* __restrict__ user0, int mode) {
    int t = blockIdx.x * blockDim.x + threadIdx.x;
    int w = t >> 3, ln = t & 7;
    if (w >= N_USERS) return;
    int s = __ldg(&offs[w]), e = __ldg(&offs[w + 1]);
    float acc[8] = {0, 0, 0, 0, 0, 0, 0, 0};
    int i = s;
    for (; i + 3 < e; i += 4) {
        int2 e0 = __ldg(&edges[i]);
        int2 e1 = __ldg(&edges[i + 1]);
        int2 e2 = __ldg(&edges[i + 2]);
        int2 e3 = __ldg(&edges[i + 3]);
        float v0 = __int_as_float(e0.y) * __ldg(&f[e0.x]);
        float v1 = __int_as_float(e1.y) * __ldg(&f[e1.x]);
        float v2 = __int_as_float(e2.y) * __ldg(&f[e2.x]);
        float v3 = __int_as_float(e3.y) * __ldg(&f[e3.x]);
        uint4 h0 = __ldg((const uint4*)(ent16 + (size_t)e0.x * D) + ln);
        uint4 h1 = __ldg((const uint4*)(ent16 + (size_t)e1.x * D) + ln);
        uint4 h2 = __ldg((const uint4*)(ent16 + (size_t)e2.x * D) + ln);
        uint4 h3 = __ldg((const uint4*)(ent16 + (size_t)e3.x * D) + ln);
        accum_hs(acc, h0, v0); accum_hs(acc, h1, v1);
        accum_hs(acc, h2, v2); accum_hs(acc, h3, v3);
    }
    for (; i < e; i++) {
        int2 e0 = __ldg(&edges[i]);
        float v0 = __int_as_float(e0.y) * __ldg(&f[e0.x]);
        uint4 h0 = __ldg((const uint4*)(ent16 + (size_t)e0.x * D) + ln);
        accum_hs(acc, h0, v0);
    }
    float sc = 1.0f / fmaxf(sqrtf(group_sumsq8(acc)), 1e-12f);
    float4* o = (float4*)(out_user + (size_t)w * D) + ln * 2;
    if (mode == 0) {
        const float4* up = (const float4*)(user0 + (size_t)w * D) + ln * 2;
        float4 u0 = __ldg(up), u1 = __ldg(up + 1);
        o[0] = make_float4(u0.x + acc[0] * sc, u0.y + acc[1] * sc,
                           u0.z + acc[2] * sc, u0.w + acc[3] * sc);
        o[1] = make_float4(u1.x + acc[4] * sc, u1.y + acc[5] * sc,
                           u1.z + acc[6] * sc, u1.w + acc[7] * sc);
    } else {
        float4 a0 = o[0], a1 = o[1];
        o[0] = make_float4(a0.x + acc[0] * sc, a0.y + acc[1] * sc,
                           a0.z + acc[2] * sc, a0.w + acc[3] * sc);
        o[1] = make_float4(a1.x + acc[4] * sc, a1.y + acc[5] * sc,
                           a1.z + acc[6] * sc, a1.w + acc[7] * sc);
    }
}

// ---------------- launch ----------------

static void build_csr(cudaStream_t st, const int* head, int E, int n,
                      int* offs, int* cursor, int* cnt, int* bsums) {
    cudaMemsetAsync(cnt, 0, n * sizeof(int), st);
    count_k<<<(E + 255) / 256, 256, 0, st>>>(head, E, cnt);
    int nb = (n + 1023) / 1024;
    scan_block_k<<<nb, 1024, 0, st>>>(cnt, n, offs, bsums);
    scan_final_k<<<1, 256, 0, st>>>(bsums, nb, offs, n, E);
    add_offs_k<<<nb, 1024, 0, st>>>(offs, cursor, bsums, n);
}

extern "C" void kernel_launch(void* const* d_in, const int* in_sizes, int n_in,
                              void* d_out, int out_size) {
    const float* user_emb         = (const float*)d_in[0];
    const float* entity_emb       = (const float*)d_in[1];
    const float* weight           = (const float*)d_in[2];
    const float* extra_weight     = (const float*)d_in[3];
    const float* interact_vals    = (const float*)d_in[4];
    const int*   edge_index       = (const int*)d_in[5];
    const int*   edge_type        = (const int*)d_in[6];
    const int*   extra_edge_index = (const int*)d_in[7];
    const int*   extra_edge_type  = (const int*)d_in[8];
    const int*   interact_idx     = (const int*)d_in[9];
    float* out = (float*)d_out;

    const int* kg_head = edge_index;
    const int* kg_tail = edge_index + E_KG;
    const int* pf_head = extra_edge_index;
    const int* pf_tail = extra_edge_index + E_PREF;
    const int* it_rows = interact_idx;
    const int* it_cols = interact_idx + NNZ;

    static cudaStream_t sA = nullptr, sB = nullptr;
    static cudaEvent_t evFork, evCE, evKG0, evIT0, evPref;
    if (!sA) {
        cudaStreamCreateWithFlags(&sA, cudaStreamNonBlocking);
        cudaStreamCreateWithFlags(&sB, cudaStreamNonBlocking);
        cudaEventCreateWithFlags(&evFork, cudaEventDisableTiming);
        cudaEventCreateWithFlags(&evCE,   cudaEventDisableTiming);
        cudaEventCreateWithFlags(&evKG0,  cudaEventDisableTiming);
        cudaEventCreateWithFlags(&evIT0,  cudaEventDisableTiming);
        cudaEventCreateWithFlags(&evPref, cudaEventDisableTiming);
    }

    __half *ent16_in, *usr16_in, *ent_b16, *ent_c16, *usr_b16, *w16, *ew16;
    float *fent_a, *fent_b;
    int *cnt_kg, *cnt_pf, *cnt_it, *bs_kg, *bs_pf, *bs_it;
    int *offs_kg, *offs_pf, *offs_it, *cur_kg, *cur_pf, *cur_it;
    unsigned *ekg, *epf;
    int2 *eit;
    cudaGetSymbolAddress((void**)&ent16_in, g_ent16_in);
    cudaGetSymbolAddress((void**)&usr16_in, g_usr16_in);
    cudaGetSymbolAddress((void**)&ent_b16,  g_ent_b16);
    cudaGetSymbolAddress((void**)&ent_c16,  g_ent_c16);
    cudaGetSymbolAddress((void**)&usr_b16,  g_usr_b16);
    cudaGetSymbolAddress((void**)&w16,      g_w16);
    cudaGetSymbolAddress((void**)&ew16,     g_ew16);
    cudaGetSymbolAddress((void**)&fent_a,   g_fent_a);
    cudaGetSymbolAddress((void**)&fent_b,   g_fent_b);
    cudaGetSymbolAddress((void**)&cnt_kg,   g_cnt_kg);
    cudaGetSymbolAddress((void**)&cnt_pf,   g_cnt_pf);
    cudaGetSymbolAddress((void**)&cnt_it,   g_cnt_it);
    cudaGetSymbolAddress((void**)&bs_kg,    g_bs_kg);
    cudaGetSymbolAddress((void**)&bs_pf,    g_bs_pf);
    cudaGetSymbolAddress((void**)&bs_it,    g_bs_it);
    cudaGetSymbolAddress((void**)&offs_kg,  g_offs_kg);
    cudaGetSymbolAddress((void**)&offs_pf,  g_offs_pf);
    cudaGetSymbolAddress((void**)&offs_it,  g_offs_it);
    cudaGetSymbolAddress((void**)&cur_kg,   g_cur_kg);
    cudaGetSymbolAddress((void**)&cur_pf,   g_cur_pf);
    cudaGetSymbolAddress((void**)&cur_it,   g_cur_it);
    cudaGetSymbolAddress((void**)&ekg,      g_ekg);
    cudaGetSymbolAddress((void**)&epf,      g_epf);
    cudaGetSymbolAddress((void**)&eit,      g_eit);

    float* out_user = out;
    float* out_ent  = out + (size_t)N_USERS * D;
    float* out_node = out + (size_t)N_NODES * D;

    const int GB_ENT  = (N_ENTITIES * 8 + 255) / 256;
    const int GB_NODE = (N_NODES    * 8 + 255) / 256;
    const int GB_USER = (N_USERS    * 8 + 255) / 256;
    const int CV_ENT  = (N_ENTITIES * D / 4 + 255) / 256;
    const int CV_USR  = (N_USERS    * D / 4 + 255) / 256;

    // ---- fork ----
    cudaEventRecord(evFork, 0);
    cudaStreamWaitEvent(sA, evFork, 0);
    cudaStreamWaitEvent(sB, evFork, 0);

    // ---- main: convert entity table + kg weights to fp16 ----
    conv16_k<<<CV_ENT, 256, 0, 0>>>(entity_emb, ent16_in, N_ENTITIES * D / 4);
    conv16_k<<<1, 256, 0, 0>>>(weight, w16, 16 * D / 4);
    cudaEventRecord(evCE, 0);

    // ---- stream B: interact CSR ----
    build_csr(sB, it_rows, NNZ, N_USERS, offs_it, cur_it, cnt_it, bs_it);
    fill_it_k<<<(NNZ + 255) / 256, 256, 0, sB>>>(it_rows, it_cols, interact_vals,
                                                 cur_it, eit);

    // ---- stream A: conversions + pref CSR + pref0 ----
    conv16_k<<<CV_USR, 256, 0, sA>>>(user_emb, usr16_in, N_USERS * D / 4);
    conv16_k<<<2, 256, 0, sA>>>(extra_weight, ew16, 32 * D / 4);
    build_csr(sA, pf_head, E_PREF, N_NODES, offs_pf, cur_pf, cnt_pf, bs_pf);
    fill_packed_k<<<(E_PREF + 255) / 256, 256, 0, sA>>>(pf_head, pf_tail, extra_edge_type,
                                                        E_PREF, 0, cur_pf, epf);
    cudaStreamWaitEvent(sA, evCE, 0);
    gather_pref_h<<<GB_NODE, 256, 0, sA>>>(usr16_in, ent16_in, ew16,
                                           offs_pf, epf, usr_b16, out_node,
                                           user_emb, entity_emb, 0);

    // ---- main: kg chain ----
    build_csr(0, kg_head, E_KG, N_ENTITIES, offs_kg, cur_kg, cnt_kg, bs_kg);
    fill_packed_k<<<(E_KG + 255) / 256, 256, 0, 0>>>(kg_head, kg_tail, edge_type,
                                                     E_KG, 1, cur_kg, ekg);

    // hop 0: entity agg
    gather_kg_h<<<GB_ENT, 256, 0, 0>>>(ent16_in, w16, offs_kg, ekg,
                                       ent_b16, nullptr, fent_a);
    cudaEventRecord(evKG0, 0);

    // hop 0 interact on stream B (parallel with kg1)
    cudaStreamWaitEvent(sB, evKG0, 0);
    gather_it_h<<<GB_USER, 256, 0, sB>>>(ent_b16, fent_a, offs_it, eit,
                                         out_user, user_emb, 0);
    cudaEventRecord(evIT0, sB);

    // hop 1 pref on stream A
    cudaStreamWaitEvent(sA, evKG0, 0);
    gather_pref_h<<<GB_NODE, 256, 0, sA>>>(usr_b16, ent_b16, ew16,
                                           offs_pf, epf, nullptr, out_node,
                                           user_emb, entity_emb, 1);
    cudaEventRecord(evPref, sA);

    // hop 1: entity agg -> out_ent (fp32) + ent_c16
    gather_kg_h<<<GB_ENT, 256, 0, 0>>>(ent_b16, w16, offs_kg, ekg,
                                       ent_c16, out_ent, fent_b);

    // hop 1 interact
    cudaStreamWaitEvent(0, evIT0, 0);
    gather_it_h<<<GB_USER, 256, 0, 0>>>(ent_c16, fent_b, offs_it, eit,
                                        out_user, user_emb, 1);

    // ---- join ----
    cudaStreamWaitEvent(0, evPref, 0);
}